// round 11
// baseline (speedup 1.0000x reference)
#include <cuda_runtime.h>
#include <cuda_bf16.h>
#include <cstdint>

#define BB 16
#define CC 512
#define TT 1024
#define NH 8
#define DH 64
#define NG 32
#define CPG 16

typedef __nv_bfloat16 bf16;

// ---------------- scratch ----------------
__device__ bf16 g_xn_h[BB * CC * TT];
__device__ bf16 g_xn_l[BB * CC * TT];
__device__ bf16 g_qkv_h[BB * 3 * CC * TT];
__device__ bf16 g_qkv_l[BB * 3 * CC * TT];
__device__ bf16 g_at_h[BB * CC * TT];
__device__ bf16 g_at_l[BB * CC * TT];
__device__ bf16 g_wq_h[3 * CC * CC];
__device__ bf16 g_wq_l[3 * CC * CC];
__device__ bf16 g_wp_h[CC * CC];
__device__ bf16 g_wp_l[CC * CC];

// ---------------- helpers ----------------
__device__ __forceinline__ uint32_t cvta_smem(const void* p) {
    uint32_t a;
    asm("{.reg .u64 t; cvta.to.shared.u64 t, %1; cvt.u32.u64 %0, t;}"
        : "=r"(a) : "l"(p));
    return a;
}
__device__ __forceinline__ void ldsm4(uint32_t* r, uint32_t addr) {
    asm volatile("ldmatrix.sync.aligned.m8n8.x4.shared.b16 {%0,%1,%2,%3},[%4];"
                 : "=r"(r[0]), "=r"(r[1]), "=r"(r[2]), "=r"(r[3]) : "r"(addr));
}
__device__ __forceinline__ void ldsm4t(uint32_t* r, uint32_t addr) {
    asm volatile("ldmatrix.sync.aligned.m8n8.x4.trans.shared.b16 {%0,%1,%2,%3},[%4];"
                 : "=r"(r[0]), "=r"(r[1]), "=r"(r[2]), "=r"(r[3]) : "r"(addr));
}
__device__ __forceinline__ void mma16816(float* c, const uint32_t* a, const uint32_t* b) {
    asm volatile(
        "mma.sync.aligned.m16n8k16.row.col.f32.bf16.bf16.f32 "
        "{%0,%1,%2,%3},{%4,%5,%6,%7},{%8,%9},{%0,%1,%2,%3};"
        : "+f"(c[0]), "+f"(c[1]), "+f"(c[2]), "+f"(c[3])
        : "r"(a[0]), "r"(a[1]), "r"(a[2]), "r"(a[3]), "r"(b[0]), "r"(b[1]));
}
__device__ __forceinline__ void cpa16(uint32_t dst, const void* src) {
    asm volatile("cp.async.cg.shared.global [%0],[%1],16;" :: "r"(dst), "l"(src));
}
__device__ __forceinline__ void cpa_commit() {
    asm volatile("cp.async.commit_group;");
}
__device__ __forceinline__ void cpa_wait0() {
    asm volatile("cp.async.wait_group 0;");
}
__device__ __forceinline__ void cpa_wait1() {
    asm volatile("cp.async.wait_group 1;");
}
union BF2U { __nv_bfloat162 h; uint32_t u; };
__device__ __forceinline__ void split2(float x, float y, uint32_t& hi, uint32_t& lo) {
    BF2U H, L;
    H.h = __floats2bfloat162_rn(x, y);
    float rx = x - __low2float(H.h);
    float ry = y - __high2float(H.h);
    L.h = __floats2bfloat162_rn(rx, ry);
    hi = H.u; lo = L.u;
}

// ---------------------------------------------------------------------------
// W pre-split: f32 -> bf16 hi/lo planes
// ---------------------------------------------------------------------------
__global__ void wsplit_kernel(const float* __restrict__ w, bf16* __restrict__ wh,
                              bf16* __restrict__ wl, int n) {
    int i = (blockIdx.x * blockDim.x + threadIdx.x) * 2;
    if (i < n) {
        uint32_t h, l;
        split2(w[i], w[i + 1], h, l);
        *(uint32_t*)&wh[i] = h;
        *(uint32_t*)&wl[i] = l;
    }
}

// ---------------------------------------------------------------------------
// GroupNorm -> bf16 hi/lo planes (R8-proven)
// ---------------------------------------------------------------------------
__global__ __launch_bounds__(256) void gn_kernel(
    const float* __restrict__ x, const float* __restrict__ scale,
    const float* __restrict__ bias, bf16* __restrict__ xnh,
    bf16* __restrict__ xnl) {
    int blk = blockIdx.x;
    int b = blk >> 5, g = blk & 31;
    size_t base = ((size_t)b * CC + (size_t)g * CPG) * TT;
    const float4* xp4 = (const float4*)(x + base);
    const int N4 = CPG * TT / 4;

    float s = 0.f, ss = 0.f;
    for (int i = threadIdx.x; i < N4; i += 256) {
        float4 v = xp4[i];
        s += v.x + v.y + v.z + v.w;
        ss += v.x * v.x + v.y * v.y + v.z * v.z + v.w * v.w;
    }
    for (int o = 16; o; o >>= 1) {
        s += __shfl_down_sync(0xffffffffu, s, o);
        ss += __shfl_down_sync(0xffffffffu, ss, o);
    }
    __shared__ float red0[8], red1[8];
    __shared__ float mean_s, inv_s;
    int warp = threadIdx.x >> 5, lane = threadIdx.x & 31;
    if (lane == 0) { red0[warp] = s; red1[warp] = ss; }
    __syncthreads();
    if (threadIdx.x == 0) {
        float S = 0.f, SS = 0.f;
        #pragma unroll
        for (int w = 0; w < 8; w++) { S += red0[w]; SS += red1[w]; }
        const float invn = 1.f / (float)(CPG * TT);
        float mean = S * invn;
        float var = SS * invn - mean * mean;
        mean_s = mean;
        inv_s = rsqrtf(var + 1e-5f);
    }
    __syncthreads();
    float mean = mean_s, inv = inv_s;
    for (int i = threadIdx.x; i < N4; i += 256) {
        int ch = g * CPG + (i >> 8);
        float sc = scale[ch] * inv, bi = bias[ch] - mean * sc;
        float4 v = xp4[i];
        v.x = v.x * sc + bi; v.y = v.y * sc + bi;
        v.z = v.z * sc + bi; v.w = v.w * sc + bi;
        uint32_t h0, l0, h1, l1;
        split2(v.x, v.y, h0, l0); split2(v.z, v.w, h1, l1);
        *(uint2*)&xnh[base + (size_t)i * 4] = make_uint2(h0, h1);
        *(uint2*)&xnl[base + (size_t)i * 4] = make_uint2(l0, l1);
    }
}

// ---------------------------------------------------------------------------
// GEMM (R8 structure): 128x128 block, 8 warps (2m x 4n), 2-stage buffer.
// Only change vs R8: A-side now cp.async from pre-split W planes.
// Static smem: 41984 B.
// ---------------------------------------------------------------------------
#define A_ST 12288u
#define A_SD 6144u
#define B_ST 8704u
#define B_SD 4352u

template <bool PO>
__global__ __launch_bounds__(256, 2) void gemm_mma(
    const bf16* __restrict__ Wh, const bf16* __restrict__ Wl,
    const bf16* __restrict__ Xh, const bf16* __restrict__ Xl,
    const float* __restrict__ bias, const float* __restrict__ res,
    float* __restrict__ outf, bf16* __restrict__ oh, bf16* __restrict__ ol,
    int M, int K) {
    const int N = TT;
    int bb = blockIdx.z;
    size_t xoff = (size_t)bb * K * N;

    __shared__ __align__(16) bf16 sA[2][2][128][24];
    __shared__ __align__(16) bf16 sB[2][2][16][136];
    const uint32_t uA = cvta_smem(sA);
    const uint32_t uB = cvta_smem(sB);

    int tid = threadIdx.x, lane = tid & 31, warp = tid >> 5;
    int wm = warp >> 2, wn = warp & 3;
    int m0 = blockIdx.y * 128, n0 = blockIdx.x * 128;
    const int NT = K / 16;

    // one group per stage: A (512 x 16B) + B (512 x 16B), 4 cpa16/thread
    auto issue = [&](int kt, int buf) {
        #pragma unroll
        for (int it = 0; it < 2; it++) {
            int e = tid + it * 256;
            int side = e >> 8, m = (e >> 1) & 127, ch = e & 1;
            const bf16* src = (side ? Wl : Wh) + (size_t)(m0 + m) * K + kt * 16 + ch * 8;
            cpa16(uA + buf * A_ST + side * A_SD + (uint32_t)(m * 24 + ch * 8) * 2, src);
        }
        #pragma unroll
        for (int it = 0; it < 2; it++) {
            int e = tid + it * 256;
            int side = e >> 8, row = (e >> 4) & 15, c16 = e & 15;
            const bf16* src = (side ? Xl : Xh) + xoff + (size_t)(kt * 16 + row) * N + n0 + c16 * 8;
            cpa16(uB + buf * B_ST + side * B_SD + (uint32_t)(row * 136 + c16 * 8) * 2, src);
        }
        cpa_commit();
    };

    uint32_t aoff[4], boff[2];
    {
        int arow = lane & 15, acol = (lane & 16) ? 8 : 0;
        #pragma unroll
        for (int mt = 0; mt < 4; mt++)
            aoff[mt] = ((wm * 64 + mt * 16 + arow) * 24 + acol) * 2;
        int bkr = lane & 15, bnc = (lane & 16) ? 8 : 0;
        #pragma unroll
        for (int h = 0; h < 2; h++)
            boff[h] = (bkr * 136 + wn * 32 + h * 16 + bnc) * 2;
    }

    float c[4][4][4];
    #pragma unroll
    for (int i = 0; i < 4; i++)
        #pragma unroll
        for (int j = 0; j < 4; j++)
            #pragma unroll
            for (int k = 0; k < 4; k++) c[i][j][k] = 0.f;

    // prologue: stage 0, R8-style wait-before-first-compute
    issue(0, 0);
    cpa_wait0();
    __syncthreads();

    for (int kt = 0; kt < NT; kt++) {
        int cur = kt & 1;
        if (kt + 1 < NT) issue(kt + 1, cur ^ 1);

        uint32_t aB = uA + cur * A_ST;
        uint32_t bB = uB + cur * B_ST;
        uint32_t bh[2][4], bl[2][4];
        #pragma unroll
        for (int h = 0; h < 2; h++) {
            ldsm4t(bh[h], bB + boff[h]);
            ldsm4t(bl[h], bB + B_SD + boff[h]);
        }
        #pragma unroll
        for (int mt = 0; mt < 4; mt++) {
            uint32_t ah[4], al[4];
            ldsm4(ah, aB + aoff[mt]);
            ldsm4(al, aB + A_SD + aoff[mt]);
            #pragma unroll
            for (int nt = 0; nt < 4; nt++) {
                uint32_t* B_h = &bh[nt >> 1][(nt & 1) * 2];
                uint32_t* B_l = &bl[nt >> 1][(nt & 1) * 2];
                mma16816(c[mt][nt], ah, B_h);
                mma16816(c[mt][nt], al, B_h);
                mma16816(c[mt][nt], ah, B_l);
            }
        }
        if (kt + 1 < NT) {
            cpa_wait0();
            __syncthreads();
        }
    }

    #pragma unroll
    for (int mt = 0; mt < 4; mt++) {
        int r0 = m0 + wm * 64 + mt * 16 + (lane >> 2);
        int r1 = r0 + 8;
        float b0v = bias[r0], b1v = bias[r1];
        #pragma unroll
        for (int nt = 0; nt < 4; nt++) {
            int cc = n0 + wn * 32 + nt * 8 + (lane & 3) * 2;
            float v00 = c[mt][nt][0] + b0v, v01 = c[mt][nt][1] + b0v;
            float v10 = c[mt][nt][2] + b1v, v11 = c[mt][nt][3] + b1v;
            size_t i0 = (size_t)bb * M * N + (size_t)r0 * N + cc;
            size_t i1 = (size_t)bb * M * N + (size_t)r1 * N + cc;
            if (PO) {
                uint32_t h, l;
                split2(v00, v01, h, l);
                *(uint32_t*)&oh[i0] = h; *(uint32_t*)&ol[i0] = l;
                split2(v10, v11, h, l);
                *(uint32_t*)&oh[i1] = h; *(uint32_t*)&ol[i1] = l;
            } else {
                float2 v0 = {v00, v01}, v1 = {v10, v11};
                if (res) {
                    float2 q0 = *(const float2*)&res[i0];
                    float2 q1 = *(const float2*)&res[i1];
                    v0.x += q0.x; v0.y += q0.y; v1.x += q1.x; v1.y += q1.y;
                }
                *(float2*)&outf[i0] = v0;
                *(float2*)&outf[i1] = v1;
            }
        }
    }
}

// ---------------------------------------------------------------------------
// Attention — EXACT R8-passing version (256 threads, 64-q tiles).
// ---------------------------------------------------------------------------
#define QSIDE 18432u       // 64*72*2 per... (R8: region per side, kept identical)
#define O_Q 0
#define O_K 36864
#define O_V 73728
#define O_P 110592
#define O_S 147456
#define O_M 182272
#define O_L 182784
#define O_AL 183296
#define ATTN_SMEM 183808
#define SIDEB (64 * 72 * 2)

__global__ __launch_bounds__(256) void attn_mma(
    const bf16* __restrict__ qkvh, const bf16* __restrict__ qkvl,
    bf16* __restrict__ ath, bf16* __restrict__ atl) {
    extern __shared__ char smem[];
    bf16* sP = (bf16*)(smem + O_P);
    float* sS = (float*)(smem + O_S);
    float* m_s = (float*)(smem + O_M);
    float* l_s = (float*)(smem + O_L);
    float* al_s = (float*)(smem + O_AL);
    const int SIDE = 64 * 72;

    const uint32_t uQ = cvta_smem(smem + O_Q);
    const uint32_t uK = cvta_smem(smem + O_K);
    const uint32_t uV = cvta_smem(smem + O_V);
    const uint32_t uP = cvta_smem(sP);

    int tid = threadIdx.x, lane = tid & 31, warp = tid >> 5;
    int wq = warp >> 1, ws = warp & 1;
    int qbase = wq * 16, sbase = ws * 32;
    int head = blockIdx.y;
    int b = head >> 3, hd = head & 7;
    int q0g = blockIdx.x * 64;

    size_t hoff = ((size_t)b * 3 * CC + (size_t)hd * 192) * TT;
    const bf16* qph = qkvh + hoff;
    const bf16* qpl = qkvl + hoff;
    const bf16* kph = qph + (size_t)64 * TT;
    const bf16* kpl = qpl + (size_t)64 * TT;
    const bf16* vph = kph + (size_t)64 * TT;
    const bf16* vpl = kpl + (size_t)64 * TT;

    int crow[2], cc16[2];
    #pragma unroll
    for (int it = 0; it < 2; it++) {
        int e = tid + it * 256;
        crow[it] = e >> 3;
        cc16[it] = e & 7;
    }

    #pragma unroll
    for (int it = 0; it < 2; it++) {
        uint32_t doff = (uint32_t)(crow[it] * 72 + cc16[it] * 8) * 2;
        size_t soff = (size_t)crow[it] * TT + q0g + cc16[it] * 8;
        cpa16(uQ + doff, qph + soff);
        cpa16(uQ + SIDEB + doff, qpl + soff);
    }
    cpa_commit();
    if (tid < 64) { m_s[tid] = -1e30f; l_s[tid] = 0.f; }

    float o[4][4];
    #pragma unroll
    for (int i = 0; i < 4; i++)
        #pragma unroll
        for (int j = 0; j < 4; j++) o[i][j] = 0.f;

    uint32_t qk_a_off = (((lane & 7) + ((lane & 16) ? 8 : 0)) * 72 +
                         qbase + ((lane & 8) ? 8 : 0)) * 2;
    uint32_t qk_b_off[2];
    #pragma unroll
    for (int h = 0; h < 2; h++)
        qk_b_off[h] = ((lane & 15) * 72 + sbase + h * 16 + ((lane & 16) ? 8 : 0)) * 2;
    uint32_t pv_a_off = ((qbase + (lane & 15)) * 72 + ((lane & 16) ? 8 : 0)) * 2;
    uint32_t pv_b_off[2];
    #pragma unroll
    for (int h = 0; h < 2; h++)
        pv_b_off[h] = ((ws * 32 + h * 16 + (lane & 7) + ((lane & 16) ? 8 : 0)) * 72 +
                       ((lane & 8) ? 8 : 0)) * 2;

    cpa_wait0();
    __syncthreads();

    uint32_t qh[4][4], ql[4][4];
    #pragma unroll
    for (int cs = 0; cs < 4; cs++) {
        uint32_t coff = cs * 16 * 72 * 2;
        ldsm4t(qh[cs], uQ + qk_a_off + coff);
        ldsm4t(ql[cs], uQ + SIDEB + qk_a_off + coff);
    }

    for (int kt = 0; kt < TT / 64; kt++) {
        int s0g = kt * 64;
        #pragma unroll
        for (int it = 0; it < 2; it++) {
            uint32_t doff = (uint32_t)(crow[it] * 72 + cc16[it] * 8) * 2;
            size_t soff = (size_t)crow[it] * TT + s0g + cc16[it] * 8;
            cpa16(uK + doff, kph + soff);
            cpa16(uK + SIDEB + doff, kpl + soff);
            cpa16(uV + doff, vph + soff);
            cpa16(uV + SIDEB + doff, vpl + soff);
        }
        cpa_commit();
        cpa_wait0();
        __syncthreads();

        // ---- QK ----
        {
            float sc[4][4];
            #pragma unroll
            for (int i = 0; i < 4; i++)
                #pragma unroll
                for (int j = 0; j < 4; j++) sc[i][j] = 0.f;
            #pragma unroll
            for (int cs = 0; cs < 4; cs++) {
                uint32_t coff = cs * 16 * 72 * 2;
                uint32_t bh[2][4], bl[2][4];
                #pragma unroll
                for (int h = 0; h < 2; h++) {
                    ldsm4t(bh[h], uK + qk_b_off[h] + coff);
                    ldsm4t(bl[h], uK + SIDEB + qk_b_off[h] + coff);
                }
                #pragma unroll
                for (int nt = 0; nt < 4; nt++) {
                    uint32_t* B_h = &bh[nt >> 1][(nt & 1) * 2];
                    uint32_t* B_l = &bl[nt >> 1][(nt & 1) * 2];
                    mma16816(sc[nt], qh[cs], B_h);
                    mma16816(sc[nt], ql[cs], B_h);
                    mma16816(sc[nt], qh[cs], B_l);
                }
            }
            int r0 = qbase + (lane >> 2);
            #pragma unroll
            for (int nt = 0; nt < 4; nt++) {
                int cc = sbase + nt * 8 + (lane & 3) * 2;
                *(float2*)&sS[r0 * 68 + cc] =
                    make_float2(sc[nt][0] * 0.125f, sc[nt][1] * 0.125f);
                *(float2*)&sS[(r0 + 8) * 68 + cc] =
                    make_float2(sc[nt][2] * 0.125f, sc[nt][3] * 0.125f);
            }
        }
        __syncthreads();

        // ---- softmax ----
        {
            int q = tid >> 2, part = tid & 3;
            float pv[16];
            #pragma unroll
            for (int j4 = 0; j4 < 4; j4++)
                *(float4*)&pv[j4 * 4] = *(const float4*)&sS[q * 68 + part * 16 + j4 * 4];
            float mprev = m_s[q];
            float mx = -1e30f;
            #pragma unroll
            for (int j = 0; j < 16; j++) mx = fmaxf(mx, pv[j]);
            mx = fmaxf(mx, __shfl_xor_sync(0xffffffffu, mx, 1));
            mx = fmaxf(mx, __shfl_xor_sync(0xffffffffu, mx, 2));
            mx = fmaxf(mx, mprev);
            float sum = 0.f;
            #pragma unroll
            for (int j = 0; j < 16; j++) { pv[j] = __expf(pv[j] - mx); sum += pv[j]; }
            sum += __shfl_xor_sync(0xffffffffu, sum, 1);
            sum += __shfl_xor_sync(0xffffffffu, sum, 2);
            #pragma unroll
            for (int j4 = 0; j4 < 4; j4++) {
                uint32_t h0, l0, h1, l1;
                split2(pv[j4 * 4], pv[j4 * 4 + 1], h0, l0);
                split2(pv[j4 * 4 + 2], pv[j4 * 4 + 3], h1, l1);
                *(uint2*)&sP[q * 72 + part * 16 + j4 * 4] = make_uint2(h0, h1);
                *(uint2*)&sP[SIDE + q * 72 + part * 16 + j4 * 4] = make_uint2(l0, l1);
            }
            if (part == 0) {
                float al = __expf(mprev - mx);
                m_s[q] = mx;
                al_s[q] = al;
                l_s[q] = l_s[q] * al + sum;
            }
        }
        __syncthreads();

        // ---- PV ----
        {
            float al0 = al_s[qbase + (lane >> 2)];
            float al1 = al_s[qbase + (lane >> 2) + 8];
            #pragma unroll
            for (int nt = 0; nt < 4; nt++) {
                o[nt][0] *= al0; o[nt][1] *= al0;
                o[nt][2] *= al1; o[nt][3] *= al1;
            }
            #pragma unroll
            for (int st = 0; st < 4; st++) {
                uint32_t soff = st * 16 * 2;
                uint32_t pah[4], pal[4], vbh[2][4], vbl[2][4];
                ldsm4(pah, uP + pv_a_off + soff);
                ldsm4(pal, uP + SIDEB + pv_a_off + soff);
                #pragma unroll
                for (int h = 0; h < 2; h++) {
                    ldsm4(vbh[h], uV + pv_b_off[h] + soff);
                    ldsm4(vbl[h], uV + SIDEB + pv_b_off[h] + soff);
                }
                #pragma unroll
                for (int nt = 0; nt < 4; nt++) {
                    uint32_t* B_h = &vbh[nt >> 1][(nt & 1) * 2];
                    uint32_t* B_l = &vbl[nt >> 1][(nt & 1) * 2];
                    mma16816(o[nt], pah, B_h);
                    mma16816(o[nt], pal, B_h);
                    mma16816(o[nt], pah, B_l);
                }
            }
        }
        __syncthreads();
    }

    // normalize + stage [c][q], split-store planes
    {
        float li0 = 1.f / l_s[qbase + (lane >> 2)];
        float li1 = 1.f / l_s[qbase + (lane >> 2) + 8];
        int qq = qbase + (lane >> 2);
        #pragma unroll
        for (int nt = 0; nt < 4; nt++) {
            int c0 = ws * 32 + nt * 8 + (lane & 3) * 2;
            sS[c0 * 68 + qq] = o[nt][0] * li0;
            sS[(c0 + 1) * 68 + qq] = o[nt][1] * li0;
            sS[c0 * 68 + qq + 8] = o[nt][2] * li1;
            sS[(c0 + 1) * 68 + qq + 8] = o[nt][3] * li1;
        }
    }
    __syncthreads();
    size_t obase = ((size_t)b * CC + (size_t)hd * 64) * TT + q0g;
    #pragma unroll
    for (int it = 0; it < 4; it++) {
        int e = tid + it * 256;
        int cch = e >> 4, q4 = e & 15;
        float4 v = *(const float4*)&sS[cch * 68 + q4 * 4];
        uint32_t h0, l0, h1, l1;
        split2(v.x, v.y, h0, l0); split2(v.z, v.w, h1, l1);
        *(uint2*)&ath[obase + (size_t)cch * TT + q4 * 4] = make_uint2(h0, h1);
        *(uint2*)&atl[obase + (size_t)cch * TT + q4 * 4] = make_uint2(l0, l1);
    }
}

// ---------------------------------------------------------------------------
extern "C" void kernel_launch(void* const* d_in, const int* in_sizes, int n_in,
                              void* d_out, int out_size) {
    const float* x = (const float*)d_in[0];
    const float* gn_scale = (const float*)d_in[1];
    const float* gn_bias = (const float*)d_in[2];
    const float* w_qkv = (const float*)d_in[3];
    const float* b_qkv = (const float*)d_in[4];
    const float* w_proj = (const float*)d_in[5];
    const float* b_proj = (const float*)d_in[6];
    float* out = (float*)d_out;

    bf16 *xnh, *xnl, *qkvh, *qkvl, *ath, *atl, *wqh, *wql, *wph, *wpl;
    cudaGetSymbolAddress((void**)&xnh, g_xn_h);
    cudaGetSymbolAddress((void**)&xnl, g_xn_l);
    cudaGetSymbolAddress((void**)&qkvh, g_qkv_h);
    cudaGetSymbolAddress((void**)&qkvl, g_qkv_l);
    cudaGetSymbolAddress((void**)&ath, g_at_h);
    cudaGetSymbolAddress((void**)&atl, g_at_l);
    cudaGetSymbolAddress((void**)&wqh, g_wq_h);
    cudaGetSymbolAddress((void**)&wql, g_wq_l);
    cudaGetSymbolAddress((void**)&wph, g_wp_h);
    cudaGetSymbolAddress((void**)&wpl, g_wp_l);

    cudaFuncSetAttribute(attn_mma, cudaFuncAttributeMaxDynamicSharedMemorySize,
                         ATTN_SMEM);

    wsplit_kernel<<<(3 * CC * CC / 2 + 255) / 256, 256>>>(w_qkv, wqh, wql, 3 * CC * CC);
    wsplit_kernel<<<(CC * CC / 2 + 255) / 256, 256>>>(w_proj, wph, wpl, CC * CC);
    gn_kernel<<<BB * NG, 256>>>(x, gn_scale, gn_bias, xnh, xnl);
    gemm_mma<true><<<dim3(TT / 128, (3 * CC) / 128, BB), 256>>>(
        wqh, wql, xnh, xnl, b_qkv, nullptr, nullptr, qkvh, qkvl, 3 * CC, CC);
    attn_mma<<<dim3(TT / 64, BB * NH), 256, ATTN_SMEM>>>(qkvh, qkvl, ath, atl);
    gemm_mma<false><<<dim3(TT / 128, CC / 128, BB), 256>>>(
        wph, wpl, ath, atl, b_proj, x, out, nullptr, nullptr, CC, CC);
}

// round 12
// speedup vs baseline: 1.6451x; 1.6451x over previous
#include <cuda_runtime.h>
#include <cuda_bf16.h>
#include <cstdint>

#define BB 16
#define CC 512
#define TT 1024
#define NH 8
#define DH 64
#define NG 32
#define CPG 16

typedef __nv_bfloat16 bf16;

// ---------------- scratch ----------------
__device__ bf16 g_xn_h[BB * CC * TT];
__device__ bf16 g_xn_l[BB * CC * TT];
__device__ bf16 g_qkv_h[BB * 3 * CC * TT];
__device__ bf16 g_qkv_l[BB * 3 * CC * TT];
__device__ bf16 g_at_h[BB * CC * TT];
__device__ bf16 g_at_l[BB * CC * TT];
__device__ bf16 g_wq_h[3 * CC * CC];
__device__ bf16 g_wq_l[3 * CC * CC];
__device__ bf16 g_wp_h[CC * CC];
__device__ bf16 g_wp_l[CC * CC];

// ---------------- helpers ----------------
__device__ __forceinline__ uint32_t cvta_smem(const void* p) {
    uint32_t a;
    asm("{.reg .u64 t; cvta.to.shared.u64 t, %1; cvt.u32.u64 %0, t;}"
        : "=r"(a) : "l"(p));
    return a;
}
__device__ __forceinline__ void ldsm4(uint32_t* r, uint32_t addr) {
    asm volatile("ldmatrix.sync.aligned.m8n8.x4.shared.b16 {%0,%1,%2,%3},[%4];"
                 : "=r"(r[0]), "=r"(r[1]), "=r"(r[2]), "=r"(r[3]) : "r"(addr));
}
__device__ __forceinline__ void ldsm4t(uint32_t* r, uint32_t addr) {
    asm volatile("ldmatrix.sync.aligned.m8n8.x4.trans.shared.b16 {%0,%1,%2,%3},[%4];"
                 : "=r"(r[0]), "=r"(r[1]), "=r"(r[2]), "=r"(r[3]) : "r"(addr));
}
__device__ __forceinline__ void mma16816(float* c, const uint32_t* a, const uint32_t* b) {
    asm volatile(
        "mma.sync.aligned.m16n8k16.row.col.f32.bf16.bf16.f32 "
        "{%0,%1,%2,%3},{%4,%5,%6,%7},{%8,%9},{%0,%1,%2,%3};"
        : "+f"(c[0]), "+f"(c[1]), "+f"(c[2]), "+f"(c[3])
        : "r"(a[0]), "r"(a[1]), "r"(a[2]), "r"(a[3]), "r"(b[0]), "r"(b[1]));
}
__device__ __forceinline__ void cpa16(uint32_t dst, const void* src) {
    asm volatile("cp.async.cg.shared.global [%0],[%1],16;" :: "r"(dst), "l"(src));
}
__device__ __forceinline__ void cpa_commit() {
    asm volatile("cp.async.commit_group;");
}
__device__ __forceinline__ void cpa_wait0() {
    asm volatile("cp.async.wait_group 0;");
}
__device__ __forceinline__ void cpa_wait1() {
    asm volatile("cp.async.wait_group 1;");
}
union BF2U { __nv_bfloat162 h; uint32_t u; };
__device__ __forceinline__ void split2(float x, float y, uint32_t& hi, uint32_t& lo) {
    BF2U H, L;
    H.h = __floats2bfloat162_rn(x, y);
    float rx = x - __low2float(H.h);
    float ry = y - __high2float(H.h);
    L.h = __floats2bfloat162_rn(rx, ry);
    hi = H.u; lo = L.u;
}

// ---------------------------------------------------------------------------
// W pre-split: f32 -> bf16 hi/lo planes
// ---------------------------------------------------------------------------
__global__ void wsplit_kernel(const float* __restrict__ w, bf16* __restrict__ wh,
                              bf16* __restrict__ wl, int n) {
    int i = (blockIdx.x * blockDim.x + threadIdx.x) * 2;
    if (i < n) {
        uint32_t h, l;
        split2(w[i], w[i + 1], h, l);
        *(uint32_t*)&wh[i] = h;
        *(uint32_t*)&wl[i] = l;
    }
}

// ---------------------------------------------------------------------------
// GroupNorm -> bf16 hi/lo planes
// ---------------------------------------------------------------------------
__global__ __launch_bounds__(256) void gn_kernel(
    const float* __restrict__ x, const float* __restrict__ scale,
    const float* __restrict__ bias, bf16* __restrict__ xnh,
    bf16* __restrict__ xnl) {
    int blk = blockIdx.x;
    int b = blk >> 5, g = blk & 31;
    size_t base = ((size_t)b * CC + (size_t)g * CPG) * TT;
    const float4* xp4 = (const float4*)(x + base);
    const int N4 = CPG * TT / 4;

    float s = 0.f, ss = 0.f;
    for (int i = threadIdx.x; i < N4; i += 256) {
        float4 v = xp4[i];
        s += v.x + v.y + v.z + v.w;
        ss += v.x * v.x + v.y * v.y + v.z * v.z + v.w * v.w;
    }
    for (int o = 16; o; o >>= 1) {
        s += __shfl_down_sync(0xffffffffu, s, o);
        ss += __shfl_down_sync(0xffffffffu, ss, o);
    }
    __shared__ float red0[8], red1[8];
    __shared__ float mean_s, inv_s;
    int warp = threadIdx.x >> 5, lane = threadIdx.x & 31;
    if (lane == 0) { red0[warp] = s; red1[warp] = ss; }
    __syncthreads();
    if (threadIdx.x == 0) {
        float S = 0.f, SS = 0.f;
        #pragma unroll
        for (int w = 0; w < 8; w++) { S += red0[w]; SS += red1[w]; }
        const float invn = 1.f / (float)(CPG * TT);
        float mean = S * invn;
        float var = SS * invn - mean * mean;
        mean_s = mean;
        inv_s = rsqrtf(var + 1e-5f);
    }
    __syncthreads();
    float mean = mean_s, inv = inv_s;
    for (int i = threadIdx.x; i < N4; i += 256) {
        int ch = g * CPG + (i >> 8);
        float sc = scale[ch] * inv, bi = bias[ch] - mean * sc;
        float4 v = xp4[i];
        v.x = v.x * sc + bi; v.y = v.y * sc + bi;
        v.z = v.z * sc + bi; v.w = v.w * sc + bi;
        uint32_t h0, l0, h1, l1;
        split2(v.x, v.y, h0, l0); split2(v.z, v.w, h1, l1);
        *(uint2*)&xnh[base + (size_t)i * 4] = make_uint2(h0, h1);
        *(uint2*)&xnl[base + (size_t)i * 4] = make_uint2(l0, l1);
    }
}

// ---------------------------------------------------------------------------
// GEMM (R11-proven): 128x128 block, 8 warps (2m x 4n), 2-stage full cp.async.
// ---------------------------------------------------------------------------
#define A_ST 12288u
#define A_SD 6144u
#define B_ST 8704u
#define B_SD 4352u

template <bool PO>
__global__ __launch_bounds__(256, 2) void gemm_mma(
    const bf16* __restrict__ Wh, const bf16* __restrict__ Wl,
    const bf16* __restrict__ Xh, const bf16* __restrict__ Xl,
    const float* __restrict__ bias, const float* __restrict__ res,
    float* __restrict__ outf, bf16* __restrict__ oh, bf16* __restrict__ ol,
    int M, int K) {
    const int N = TT;
    int bb = blockIdx.z;
    size_t xoff = (size_t)bb * K * N;

    __shared__ __align__(16) bf16 sA[2][2][128][24];
    __shared__ __align__(16) bf16 sB[2][2][16][136];
    const uint32_t uA = cvta_smem(sA);
    const uint32_t uB = cvta_smem(sB);

    int tid = threadIdx.x, lane = tid & 31, warp = tid >> 5;
    int wm = warp >> 2, wn = warp & 3;
    int m0 = blockIdx.y * 128, n0 = blockIdx.x * 128;
    const int NT = K / 16;

    auto issue = [&](int kt, int buf) {
        #pragma unroll
        for (int it = 0; it < 2; it++) {
            int e = tid + it * 256;
            int side = e >> 8, m = (e >> 1) & 127, ch = e & 1;
            const bf16* src = (side ? Wl : Wh) + (size_t)(m0 + m) * K + kt * 16 + ch * 8;
            cpa16(uA + buf * A_ST + side * A_SD + (uint32_t)(m * 24 + ch * 8) * 2, src);
        }
        #pragma unroll
        for (int it = 0; it < 2; it++) {
            int e = tid + it * 256;
            int side = e >> 8, row = (e >> 4) & 15, c16 = e & 15;
            const bf16* src = (side ? Xl : Xh) + xoff + (size_t)(kt * 16 + row) * N + n0 + c16 * 8;
            cpa16(uB + buf * B_ST + side * B_SD + (uint32_t)(row * 136 + c16 * 8) * 2, src);
        }
        cpa_commit();
    };

    uint32_t aoff[4], boff[2];
    {
        int arow = lane & 15, acol = (lane & 16) ? 8 : 0;
        #pragma unroll
        for (int mt = 0; mt < 4; mt++)
            aoff[mt] = ((wm * 64 + mt * 16 + arow) * 24 + acol) * 2;
        int bkr = lane & 15, bnc = (lane & 16) ? 8 : 0;
        #pragma unroll
        for (int h = 0; h < 2; h++)
            boff[h] = (bkr * 136 + wn * 32 + h * 16 + bnc) * 2;
    }

    float c[4][4][4];
    #pragma unroll
    for (int i = 0; i < 4; i++)
        #pragma unroll
        for (int j = 0; j < 4; j++)
            #pragma unroll
            for (int k = 0; k < 4; k++) c[i][j][k] = 0.f;

    issue(0, 0);
    cpa_wait0();
    __syncthreads();

    for (int kt = 0; kt < NT; kt++) {
        int cur = kt & 1;
        if (kt + 1 < NT) issue(kt + 1, cur ^ 1);

        uint32_t aB = uA + cur * A_ST;
        uint32_t bB = uB + cur * B_ST;
        uint32_t bh[2][4], bl[2][4];
        #pragma unroll
        for (int h = 0; h < 2; h++) {
            ldsm4t(bh[h], bB + boff[h]);
            ldsm4t(bl[h], bB + B_SD + boff[h]);
        }
        #pragma unroll
        for (int mt = 0; mt < 4; mt++) {
            uint32_t ah[4], al[4];
            ldsm4(ah, aB + aoff[mt]);
            ldsm4(al, aB + A_SD + aoff[mt]);
            #pragma unroll
            for (int nt = 0; nt < 4; nt++) {
                uint32_t* B_h = &bh[nt >> 1][(nt & 1) * 2];
                uint32_t* B_l = &bl[nt >> 1][(nt & 1) * 2];
                mma16816(c[mt][nt], ah, B_h);
                mma16816(c[mt][nt], al, B_h);
                mma16816(c[mt][nt], ah, B_l);
            }
        }
        if (kt + 1 < NT) {
            cpa_wait0();
            __syncthreads();
        }
    }

    #pragma unroll
    for (int mt = 0; mt < 4; mt++) {
        int r0 = m0 + wm * 64 + mt * 16 + (lane >> 2);
        int r1 = r0 + 8;
        float b0v = bias[r0], b1v = bias[r1];
        #pragma unroll
        for (int nt = 0; nt < 4; nt++) {
            int cc = n0 + wn * 32 + nt * 8 + (lane & 3) * 2;
            float v00 = c[mt][nt][0] + b0v, v01 = c[mt][nt][1] + b0v;
            float v10 = c[mt][nt][2] + b1v, v11 = c[mt][nt][3] + b1v;
            size_t i0 = (size_t)bb * M * N + (size_t)r0 * N + cc;
            size_t i1 = (size_t)bb * M * N + (size_t)r1 * N + cc;
            if (PO) {
                uint32_t h, l;
                split2(v00, v01, h, l);
                *(uint32_t*)&oh[i0] = h; *(uint32_t*)&ol[i0] = l;
                split2(v10, v11, h, l);
                *(uint32_t*)&oh[i1] = h; *(uint32_t*)&ol[i1] = l;
            } else {
                float2 v0 = {v00, v01}, v1 = {v10, v11};
                if (res) {
                    float2 q0 = *(const float2*)&res[i0];
                    float2 q1 = *(const float2*)&res[i1];
                    v0.x += q0.x; v0.y += q0.y; v1.x += q1.x; v1.y += q1.y;
                }
                *(float2*)&outf[i0] = v0;
                *(float2*)&outf[i1] = v1;
            }
        }
    }
}

// ---------------------------------------------------------------------------
// Attention — R8 geometry (256 threads, 64-q tiles), NOW with double-buffered
// K/V (the regions were already sized 2x; offsets unchanged).
// ---------------------------------------------------------------------------
#define O_Q 0
#define O_K 36864
#define O_V 73728
#define O_P 110592
#define O_S 147456
#define O_M 182272
#define O_L 182784
#define O_AL 183296
#define ATTN_SMEM 183808
#define SIDEB (64 * 72 * 2)     // 9216 B: one side (hi or lo) of one tile
#define KVBUF (2 * SIDEB)       // 18432 B: one double-buffer slot (both sides)

__global__ __launch_bounds__(256) void attn_mma(
    const bf16* __restrict__ qkvh, const bf16* __restrict__ qkvl,
    bf16* __restrict__ ath, bf16* __restrict__ atl) {
    extern __shared__ char smem[];
    bf16* sP = (bf16*)(smem + O_P);
    float* sS = (float*)(smem + O_S);
    float* m_s = (float*)(smem + O_M);
    float* l_s = (float*)(smem + O_L);
    float* al_s = (float*)(smem + O_AL);
    const int SIDE = 64 * 72;

    const uint32_t uQ = cvta_smem(smem + O_Q);
    const uint32_t uK = cvta_smem(smem + O_K);
    const uint32_t uV = cvta_smem(smem + O_V);
    const uint32_t uP = cvta_smem(sP);

    int tid = threadIdx.x, lane = tid & 31, warp = tid >> 5;
    int wq = warp >> 1, ws = warp & 1;
    int qbase = wq * 16, sbase = ws * 32;
    int head = blockIdx.y;
    int b = head >> 3, hd = head & 7;
    int q0g = blockIdx.x * 64;

    size_t hoff = ((size_t)b * 3 * CC + (size_t)hd * 192) * TT;
    const bf16* qph = qkvh + hoff;
    const bf16* qpl = qkvl + hoff;
    const bf16* kph = qph + (size_t)64 * TT;
    const bf16* kpl = qpl + (size_t)64 * TT;
    const bf16* vph = kph + (size_t)64 * TT;
    const bf16* vpl = kpl + (size_t)64 * TT;

    int crow[2], cc16[2];
    #pragma unroll
    for (int it = 0; it < 2; it++) {
        int e = tid + it * 256;
        crow[it] = e >> 3;
        cc16[it] = e & 7;
    }

    auto issueKV = [&](int kt, int buf) {
        int s0g = kt * 64;
        #pragma unroll
        for (int it = 0; it < 2; it++) {
            uint32_t doff = (uint32_t)buf * KVBUF + (uint32_t)(crow[it] * 72 + cc16[it] * 8) * 2;
            size_t soff = (size_t)crow[it] * TT + s0g + cc16[it] * 8;
            cpa16(uK + doff, kph + soff);
            cpa16(uK + SIDEB + doff, kpl + soff);
            cpa16(uV + doff, vph + soff);
            cpa16(uV + SIDEB + doff, vpl + soff);
        }
        cpa_commit();
    };

    // group 0: Q + KV(0) ; group 1: KV(1)
    #pragma unroll
    for (int it = 0; it < 2; it++) {
        uint32_t doff = (uint32_t)(crow[it] * 72 + cc16[it] * 8) * 2;
        size_t soff = (size_t)crow[it] * TT + q0g + cc16[it] * 8;
        cpa16(uQ + doff, qph + soff);
        cpa16(uQ + SIDEB + doff, qpl + soff);
    }
    {
        int s0g = 0;
        #pragma unroll
        for (int it = 0; it < 2; it++) {
            uint32_t doff = (uint32_t)(crow[it] * 72 + cc16[it] * 8) * 2;
            size_t soff = (size_t)crow[it] * TT + s0g + cc16[it] * 8;
            cpa16(uK + doff, kph + soff);
            cpa16(uK + SIDEB + doff, kpl + soff);
            cpa16(uV + doff, vph + soff);
            cpa16(uV + SIDEB + doff, vpl + soff);
        }
    }
    cpa_commit();
    issueKV(1, 1);

    if (tid < 64) { m_s[tid] = -1e30f; l_s[tid] = 0.f; }

    float o[4][4];
    #pragma unroll
    for (int i = 0; i < 4; i++)
        #pragma unroll
        for (int j = 0; j < 4; j++) o[i][j] = 0.f;

    uint32_t qk_a_off = (((lane & 7) + ((lane & 16) ? 8 : 0)) * 72 +
                         qbase + ((lane & 8) ? 8 : 0)) * 2;
    uint32_t qk_b_off[2];
    #pragma unroll
    for (int h = 0; h < 2; h++)
        qk_b_off[h] = ((lane & 15) * 72 + sbase + h * 16 + ((lane & 16) ? 8 : 0)) * 2;
    uint32_t pv_a_off = ((qbase + (lane & 15)) * 72 + ((lane & 16) ? 8 : 0)) * 2;
    uint32_t pv_b_off[2];
    #pragma unroll
    for (int h = 0; h < 2; h++)
        pv_b_off[h] = ((ws * 32 + h * 16 + (lane & 7) + ((lane & 16) ? 8 : 0)) * 72 +
                       ((lane & 8) ? 8 : 0)) * 2;

    cpa_wait1();          // group 0 (Q + KV0) complete
    __syncthreads();

    // hoist Q fragments (Q smem never overwritten)
    uint32_t qh[4][4], ql[4][4];
    #pragma unroll
    for (int cs = 0; cs < 4; cs++) {
        uint32_t coff = cs * 16 * 72 * 2;
        ldsm4t(qh[cs], uQ + qk_a_off + coff);
        ldsm4t(ql[cs], uQ + SIDEB + qk_a_off + coff);
    }

    const int NKT = TT / 64;
    for (int kt = 0; kt < NKT; kt++) {
        int cur = kt & 1;
        uint32_t uKb = uK + cur * KVBUF;
        uint32_t uVb = uV + cur * KVBUF;

        // ---- QK ----
        {
            float sc[4][4];
            #pragma unroll
            for (int i = 0; i < 4; i++)
                #pragma unroll
                for (int j = 0; j < 4; j++) sc[i][j] = 0.f;
            #pragma unroll
            for (int cs = 0; cs < 4; cs++) {
                uint32_t coff = cs * 16 * 72 * 2;
                uint32_t bh[2][4], bl[2][4];
                #pragma unroll
                for (int h = 0; h < 2; h++) {
                    ldsm4t(bh[h], uKb + qk_b_off[h] + coff);
                    ldsm4t(bl[h], uKb + SIDEB + qk_b_off[h] + coff);
                }
                #pragma unroll
                for (int nt = 0; nt < 4; nt++) {
                    uint32_t* B_h = &bh[nt >> 1][(nt & 1) * 2];
                    uint32_t* B_l = &bl[nt >> 1][(nt & 1) * 2];
                    mma16816(sc[nt], qh[cs], B_h);
                    mma16816(sc[nt], ql[cs], B_h);
                    mma16816(sc[nt], qh[cs], B_l);
                }
            }
            int r0 = qbase + (lane >> 2);
            #pragma unroll
            for (int nt = 0; nt < 4; nt++) {
                int cc = sbase + nt * 8 + (lane & 3) * 2;
                *(float2*)&sS[r0 * 68 + cc] =
                    make_float2(sc[nt][0] * 0.125f, sc[nt][1] * 0.125f);
                *(float2*)&sS[(r0 + 8) * 68 + cc] =
                    make_float2(sc[nt][2] * 0.125f, sc[nt][3] * 0.125f);
            }
        }
        __syncthreads();

        // ---- softmax ----
        {
            int q = tid >> 2, part = tid & 3;
            float pv[16];
            #pragma unroll
            for (int j4 = 0; j4 < 4; j4++)
                *(float4*)&pv[j4 * 4] = *(const float4*)&sS[q * 68 + part * 16 + j4 * 4];
            float mprev = m_s[q];
            float mx = -1e30f;
            #pragma unroll
            for (int j = 0; j < 16; j++) mx = fmaxf(mx, pv[j]);
            mx = fmaxf(mx, __shfl_xor_sync(0xffffffffu, mx, 1));
            mx = fmaxf(mx, __shfl_xor_sync(0xffffffffu, mx, 2));
            mx = fmaxf(mx, mprev);
            float sum = 0.f;
            #pragma unroll
            for (int j = 0; j < 16; j++) { pv[j] = __expf(pv[j] - mx); sum += pv[j]; }
            sum += __shfl_xor_sync(0xffffffffu, sum, 1);
            sum += __shfl_xor_sync(0xffffffffu, sum, 2);
            #pragma unroll
            for (int j4 = 0; j4 < 4; j4++) {
                uint32_t h0, l0, h1, l1;
                split2(pv[j4 * 4], pv[j4 * 4 + 1], h0, l0);
                split2(pv[j4 * 4 + 2], pv[j4 * 4 + 3], h1, l1);
                *(uint2*)&sP[q * 72 + part * 16 + j4 * 4] = make_uint2(h0, h1);
                *(uint2*)&sP[SIDE + q * 72 + part * 16 + j4 * 4] = make_uint2(l0, l1);
            }
            if (part == 0) {
                float al = __expf(mprev - mx);
                m_s[q] = mx;
                al_s[q] = al;
                l_s[q] = l_s[q] * al + sum;
            }
        }
        __syncthreads();

        // ---- PV ----
        {
            float al0 = al_s[qbase + (lane >> 2)];
            float al1 = al_s[qbase + (lane >> 2) + 8];
            #pragma unroll
            for (int nt = 0; nt < 4; nt++) {
                o[nt][0] *= al0; o[nt][1] *= al0;
                o[nt][2] *= al1; o[nt][3] *= al1;
            }
            #pragma unroll
            for (int st = 0; st < 4; st++) {
                uint32_t soff = st * 16 * 2;
                uint32_t pah[4], pal[4], vbh[2][4], vbl[2][4];
                ldsm4(pah, uP + pv_a_off + soff);
                ldsm4(pal, uP + SIDEB + pv_a_off + soff);
                #pragma unroll
                for (int h = 0; h < 2; h++) {
                    ldsm4(vbh[h], uVb + pv_b_off[h] + soff);
                    ldsm4(vbl[h], uVb + SIDEB + pv_b_off[h] + soff);
                }
                #pragma unroll
                for (int nt = 0; nt < 4; nt++) {
                    uint32_t* B_h = &vbh[nt >> 1][(nt & 1) * 2];
                    uint32_t* B_l = &vbl[nt >> 1][(nt & 1) * 2];
                    mma16816(o[nt], pah, B_h);
                    mma16816(o[nt], pal, B_h);
                    mma16816(o[nt], pah, B_l);
                }
            }
        }
        __syncthreads();   // all warps done reading buffer `cur`

        // refill the freed buffer with kt+2, then wait for kt+1's group
        if (kt + 2 < NKT) issueKV(kt + 2, cur);
        if (kt + 1 < NKT) {
            if (kt + 2 < NKT) cpa_wait1(); else cpa_wait0();
            __syncthreads();
        }
    }

    // normalize + stage [c][q], split-store planes
    {
        float li0 = 1.f / l_s[qbase + (lane >> 2)];
        float li1 = 1.f / l_s[qbase + (lane >> 2) + 8];
        int qq = qbase + (lane >> 2);
        #pragma unroll
        for (int nt = 0; nt < 4; nt++) {
            int c0 = ws * 32 + nt * 8 + (lane & 3) * 2;
            sS[c0 * 68 + qq] = o[nt][0] * li0;
            sS[(c0 + 1) * 68 + qq] = o[nt][1] * li0;
            sS[c0 * 68 + qq + 8] = o[nt][2] * li1;
            sS[(c0 + 1) * 68 + qq + 8] = o[nt][3] * li1;
        }
    }
    __syncthreads();
    size_t obase = ((size_t)b * CC + (size_t)hd * 64) * TT + q0g;
    #pragma unroll
    for (int it = 0; it < 4; it++) {
        int e = tid + it * 256;
        int cch = e >> 4, q4 = e & 15;
        float4 v = *(const float4*)&sS[cch * 68 + q4 * 4];
        uint32_t h0, l0, h1, l1;
        split2(v.x, v.y, h0, l0); split2(v.z, v.w, h1, l1);
        *(uint2*)&ath[obase + (size_t)cch * TT + q4 * 4] = make_uint2(h0, h1);
        *(uint2*)&atl[obase + (size_t)cch * TT + q4 * 4] = make_uint2(l0, l1);
    }
}

// ---------------------------------------------------------------------------
extern "C" void kernel_launch(void* const* d_in, const int* in_sizes, int n_in,
                              void* d_out, int out_size) {
    const float* x = (const float*)d_in[0];
    const float* gn_scale = (const float*)d_in[1];
    const float* gn_bias = (const float*)d_in[2];
    const float* w_qkv = (const float*)d_in[3];
    const float* b_qkv = (const float*)d_in[4];
    const float* w_proj = (const float*)d_in[5];
    const float* b_proj = (const float*)d_in[6];
    float* out = (float*)d_out;

    bf16 *xnh, *xnl, *qkvh, *qkvl, *ath, *atl, *wqh, *wql, *wph, *wpl;
    cudaGetSymbolAddress((void**)&xnh, g_xn_h);
    cudaGetSymbolAddress((void**)&xnl, g_xn_l);
    cudaGetSymbolAddress((void**)&qkvh, g_qkv_h);
    cudaGetSymbolAddress((void**)&qkvl, g_qkv_l);
    cudaGetSymbolAddress((void**)&ath, g_at_h);
    cudaGetSymbolAddress((void**)&atl, g_at_l);
    cudaGetSymbolAddress((void**)&wqh, g_wq_h);
    cudaGetSymbolAddress((void**)&wql, g_wq_l);
    cudaGetSymbolAddress((void**)&wph, g_wp_h);
    cudaGetSymbolAddress((void**)&wpl, g_wp_l);

    cudaFuncSetAttribute(attn_mma, cudaFuncAttributeMaxDynamicSharedMemorySize,
                         ATTN_SMEM);

    wsplit_kernel<<<(3 * CC * CC / 2 + 255) / 256, 256>>>(w_qkv, wqh, wql, 3 * CC * CC);
    wsplit_kernel<<<(CC * CC / 2 + 255) / 256, 256>>>(w_proj, wph, wpl, CC * CC);
    gn_kernel<<<BB * NG, 256>>>(x, gn_scale, gn_bias, xnh, xnl);
    gemm_mma<true><<<dim3(TT / 128, (3 * CC) / 128, BB), 256>>>(
        wqh, wql, xnh, xnl, b_qkv, nullptr, nullptr, qkvh, qkvl, 3 * CC, CC);
    attn_mma<<<dim3(TT / 64, BB * NH), 256, ATTN_SMEM>>>(qkvh, qkvl, ath, atl);
    gemm_mma<false><<<dim3(TT / 128, CC / 128, BB), 256>>>(
        wph, wpl, ath, atl, b_proj, x, out, nullptr, nullptr, CC, CC);
}

// round 14
// speedup vs baseline: 1.8410x; 1.1191x over previous
#include <cuda_runtime.h>
#include <cuda_bf16.h>
#include <cstdint>

#define BB 16
#define CC 512
#define TT 1024
#define NH 8
#define DH 64
#define NG 32
#define CPG 16

typedef __nv_bfloat16 bf16;

// ---------------- scratch ----------------
__device__ bf16 g_xn_h[BB * CC * TT];
__device__ bf16 g_xn_l[BB * CC * TT];
__device__ bf16 g_qkv_h[BB * 3 * CC * TT];
__device__ bf16 g_qkv_l[BB * 3 * CC * TT];
__device__ bf16 g_at_h[BB * CC * TT];
__device__ bf16 g_at_l[BB * CC * TT];
__device__ bf16 g_wq_h[3 * CC * CC];
__device__ bf16 g_wq_l[3 * CC * CC];
__device__ bf16 g_wp_h[CC * CC];
__device__ bf16 g_wp_l[CC * CC];

// ---------------- helpers ----------------
__device__ __forceinline__ uint32_t cvta_smem(const void* p) {
    uint32_t a;
    asm("{.reg .u64 t; cvta.to.shared.u64 t, %1; cvt.u32.u64 %0, t;}"
        : "=r"(a) : "l"(p));
    return a;
}
__device__ __forceinline__ void ldsm4(uint32_t* r, uint32_t addr) {
    asm volatile("ldmatrix.sync.aligned.m8n8.x4.shared.b16 {%0,%1,%2,%3},[%4];"
                 : "=r"(r[0]), "=r"(r[1]), "=r"(r[2]), "=r"(r[3]) : "r"(addr));
}
__device__ __forceinline__ void ldsm4t(uint32_t* r, uint32_t addr) {
    asm volatile("ldmatrix.sync.aligned.m8n8.x4.trans.shared.b16 {%0,%1,%2,%3},[%4];"
                 : "=r"(r[0]), "=r"(r[1]), "=r"(r[2]), "=r"(r[3]) : "r"(addr));
}
__device__ __forceinline__ void mma16816(float* c, const uint32_t* a, const uint32_t* b) {
    asm volatile(
        "mma.sync.aligned.m16n8k16.row.col.f32.bf16.bf16.f32 "
        "{%0,%1,%2,%3},{%4,%5,%6,%7},{%8,%9},{%0,%1,%2,%3};"
        : "+f"(c[0]), "+f"(c[1]), "+f"(c[2]), "+f"(c[3])
        : "r"(a[0]), "r"(a[1]), "r"(a[2]), "r"(a[3]), "r"(b[0]), "r"(b[1]));
}
__device__ __forceinline__ void cpa16(uint32_t dst, const void* src) {
    asm volatile("cp.async.cg.shared.global [%0],[%1],16;" :: "r"(dst), "l"(src));
}
__device__ __forceinline__ void cpa_commit() {
    asm volatile("cp.async.commit_group;");
}
__device__ __forceinline__ void cpa_wait0() {
    asm volatile("cp.async.wait_group 0;");
}
union BF2U { __nv_bfloat162 h; uint32_t u; };
__device__ __forceinline__ void split2(float x, float y, uint32_t& hi, uint32_t& lo) {
    BF2U H, L;
    H.h = __floats2bfloat162_rn(x, y);
    float rx = x - __low2float(H.h);
    float ry = y - __high2float(H.h);
    L.h = __floats2bfloat162_rn(rx, ry);
    hi = H.u; lo = L.u;
}

// ---------------------------------------------------------------------------
// W pre-split: f32 -> bf16 hi/lo planes
// ---------------------------------------------------------------------------
__global__ void wsplit_kernel(const float* __restrict__ w, bf16* __restrict__ wh,
                              bf16* __restrict__ wl, int n) {
    int i = (blockIdx.x * blockDim.x + threadIdx.x) * 2;
    if (i < n) {
        uint32_t h, l;
        split2(w[i], w[i + 1], h, l);
        *(uint32_t*)&wh[i] = h;
        *(uint32_t*)&wl[i] = l;
    }
}

// ---------------------------------------------------------------------------
// GroupNorm -> bf16 hi/lo planes
// ---------------------------------------------------------------------------
__global__ __launch_bounds__(256) void gn_kernel(
    const float* __restrict__ x, const float* __restrict__ scale,
    const float* __restrict__ bias, bf16* __restrict__ xnh,
    bf16* __restrict__ xnl) {
    int blk = blockIdx.x;
    int b = blk >> 5, g = blk & 31;
    size_t base = ((size_t)b * CC + (size_t)g * CPG) * TT;
    const float4* xp4 = (const float4*)(x + base);
    const int N4 = CPG * TT / 4;

    float s = 0.f, ss = 0.f;
    for (int i = threadIdx.x; i < N4; i += 256) {
        float4 v = xp4[i];
        s += v.x + v.y + v.z + v.w;
        ss += v.x * v.x + v.y * v.y + v.z * v.z + v.w * v.w;
    }
    for (int o = 16; o; o >>= 1) {
        s += __shfl_down_sync(0xffffffffu, s, o);
        ss += __shfl_down_sync(0xffffffffu, ss, o);
    }
    __shared__ float red0[8], red1[8];
    __shared__ float mean_s, inv_s;
    int warp = threadIdx.x >> 5, lane = threadIdx.x & 31;
    if (lane == 0) { red0[warp] = s; red1[warp] = ss; }
    __syncthreads();
    if (threadIdx.x == 0) {
        float S = 0.f, SS = 0.f;
        #pragma unroll
        for (int w = 0; w < 8; w++) { S += red0[w]; SS += red1[w]; }
        const float invn = 1.f / (float)(CPG * TT);
        float mean = S * invn;
        float var = SS * invn - mean * mean;
        mean_s = mean;
        inv_s = rsqrtf(var + 1e-5f);
    }
    __syncthreads();
    float mean = mean_s, inv = inv_s;
    for (int i = threadIdx.x; i < N4; i += 256) {
        int ch = g * CPG + (i >> 8);
        float sc = scale[ch] * inv, bi = bias[ch] - mean * sc;
        float4 v = xp4[i];
        v.x = v.x * sc + bi; v.y = v.y * sc + bi;
        v.z = v.z * sc + bi; v.w = v.w * sc + bi;
        uint32_t h0, l0, h1, l1;
        split2(v.x, v.y, h0, l0); split2(v.z, v.w, h1, l1);
        *(uint2*)&xnh[base + (size_t)i * 4] = make_uint2(h0, h1);
        *(uint2*)&xnl[base + (size_t)i * 4] = make_uint2(l0, l1);
    }
}

// ---------------------------------------------------------------------------
// GEMM (R12-proven, unchanged): 128x128 block, 8 warps, 2-stage full cp.async.
// ---------------------------------------------------------------------------
#define A_ST 12288u
#define A_SD 6144u
#define B_ST 8704u
#define B_SD 4352u

template <bool PO>
__global__ __launch_bounds__(256, 2) void gemm_mma(
    const bf16* __restrict__ Wh, const bf16* __restrict__ Wl,
    const bf16* __restrict__ Xh, const bf16* __restrict__ Xl,
    const float* __restrict__ bias, const float* __restrict__ res,
    float* __restrict__ outf, bf16* __restrict__ oh, bf16* __restrict__ ol,
    int M, int K) {
    const int N = TT;
    int bb = blockIdx.z;
    size_t xoff = (size_t)bb * K * N;

    __shared__ __align__(16) bf16 sA[2][2][128][24];
    __shared__ __align__(16) bf16 sB[2][2][16][136];
    const uint32_t uA = cvta_smem(sA);
    const uint32_t uB = cvta_smem(sB);

    int tid = threadIdx.x, lane = tid & 31, warp = tid >> 5;
    int wm = warp >> 2, wn = warp & 3;
    int m0 = blockIdx.y * 128, n0 = blockIdx.x * 128;
    const int NT = K / 16;

    auto issue = [&](int kt, int buf) {
        #pragma unroll
        for (int it = 0; it < 2; it++) {
            int e = tid + it * 256;
            int side = e >> 8, m = (e >> 1) & 127, ch = e & 1;
            const bf16* src = (side ? Wl : Wh) + (size_t)(m0 + m) * K + kt * 16 + ch * 8;
            cpa16(uA + buf * A_ST + side * A_SD + (uint32_t)(m * 24 + ch * 8) * 2, src);
        }
        #pragma unroll
        for (int it = 0; it < 2; it++) {
            int e = tid + it * 256;
            int side = e >> 8, row = (e >> 4) & 15, c16 = e & 15;
            const bf16* src = (side ? Xl : Xh) + xoff + (size_t)(kt * 16 + row) * N + n0 + c16 * 8;
            cpa16(uB + buf * B_ST + side * B_SD + (uint32_t)(row * 136 + c16 * 8) * 2, src);
        }
        cpa_commit();
    };

    uint32_t aoff[4], boff[2];
    {
        int arow = lane & 15, acol = (lane & 16) ? 8 : 0;
        #pragma unroll
        for (int mt = 0; mt < 4; mt++)
            aoff[mt] = ((wm * 64 + mt * 16 + arow) * 24 + acol) * 2;
        int bkr = lane & 15, bnc = (lane & 16) ? 8 : 0;
        #pragma unroll
        for (int h = 0; h < 2; h++)
            boff[h] = (bkr * 136 + wn * 32 + h * 16 + bnc) * 2;
    }

    float c[4][4][4];
    #pragma unroll
    for (int i = 0; i < 4; i++)
        #pragma unroll
        for (int j = 0; j < 4; j++)
            #pragma unroll
            for (int k = 0; k < 4; k++) c[i][j][k] = 0.f;

    issue(0, 0);
    cpa_wait0();
    __syncthreads();

    for (int kt = 0; kt < NT; kt++) {
        int cur = kt & 1;
        if (kt + 1 < NT) issue(kt + 1, cur ^ 1);

        uint32_t aB = uA + cur * A_ST;
        uint32_t bB = uB + cur * B_ST;
        uint32_t bh[2][4], bl[2][4];
        #pragma unroll
        for (int h = 0; h < 2; h++) {
            ldsm4t(bh[h], bB + boff[h]);
            ldsm4t(bl[h], bB + B_SD + boff[h]);
        }
        #pragma unroll
        for (int mt = 0; mt < 4; mt++) {
            uint32_t ah[4], al[4];
            ldsm4(ah, aB + aoff[mt]);
            ldsm4(al, aB + A_SD + aoff[mt]);
            #pragma unroll
            for (int nt = 0; nt < 4; nt++) {
                uint32_t* B_h = &bh[nt >> 1][(nt & 1) * 2];
                uint32_t* B_l = &bl[nt >> 1][(nt & 1) * 2];
                mma16816(c[mt][nt], ah, B_h);
                mma16816(c[mt][nt], al, B_h);
                mma16816(c[mt][nt], ah, B_l);
            }
        }
        if (kt + 1 < NT) {
            cpa_wait0();
            __syncthreads();
        }
    }

    #pragma unroll
    for (int mt = 0; mt < 4; mt++) {
        int r0 = m0 + wm * 64 + mt * 16 + (lane >> 2);
        int r1 = r0 + 8;
        float b0v = bias[r0], b1v = bias[r1];
        #pragma unroll
        for (int nt = 0; nt < 4; nt++) {
            int cc = n0 + wn * 32 + nt * 8 + (lane & 3) * 2;
            float v00 = c[mt][nt][0] + b0v, v01 = c[mt][nt][1] + b0v;
            float v10 = c[mt][nt][2] + b1v, v11 = c[mt][nt][3] + b1v;
            size_t i0 = (size_t)bb * M * N + (size_t)r0 * N + cc;
            size_t i1 = (size_t)bb * M * N + (size_t)r1 * N + cc;
            if (PO) {
                uint32_t h, l;
                split2(v00, v01, h, l);
                *(uint32_t*)&oh[i0] = h; *(uint32_t*)&ol[i0] = l;
                split2(v10, v11, h, l);
                *(uint32_t*)&oh[i1] = h; *(uint32_t*)&ol[i1] = l;
            } else {
                float2 v0 = {v00, v01}, v1 = {v10, v11};
                if (res) {
                    float2 q0 = *(const float2*)&res[i0];
                    float2 q1 = *(const float2*)&res[i1];
                    v0.x += q0.x; v0.y += q0.y; v1.x += q1.x; v1.y += q1.y;
                }
                *(float2*)&outf[i0] = v0;
                *(float2*)&outf[i1] = v1;
            }
        }
    }
}

// ---------------------------------------------------------------------------
// Attention — R8-proven geometry/flow (256 threads, 64-q tiles, single-buffer)
// with COMPACT smem map: 91904 B -> 2 CTAs/SM for cross-CTA overlap.
// ---------------------------------------------------------------------------
#define O_Q 0
#define O_K 18432
#define O_V 36864
#define O_P 55296
#define O_S 73728
#define O_M 91136
#define O_L 91392
#define O_AL 91648
#define ATTN_SMEM 91904
#define SIDEB (64 * 72 * 2)

__global__ __launch_bounds__(256, 2) void attn_mma(
    const bf16* __restrict__ qkvh, const bf16* __restrict__ qkvl,
    bf16* __restrict__ ath, bf16* __restrict__ atl) {
    extern __shared__ char smem[];
    bf16* sP = (bf16*)(smem + O_P);
    float* sS = (float*)(smem + O_S);
    float* m_s = (float*)(smem + O_M);
    float* l_s = (float*)(smem + O_L);
    float* al_s = (float*)(smem + O_AL);
    const int SIDE = 64 * 72;

    const uint32_t uQ = cvta_smem(smem + O_Q);
    const uint32_t uK = cvta_smem(smem + O_K);
    const uint32_t uV = cvta_smem(smem + O_V);
    const uint32_t uP = cvta_smem(sP);

    int tid = threadIdx.x, lane = tid & 31, warp = tid >> 5;
    int wq = warp >> 1, ws = warp & 1;
    int qbase = wq * 16, sbase = ws * 32;
    int head = blockIdx.y;
    int b = head >> 3, hd = head & 7;
    int q0g = blockIdx.x * 64;

    size_t hoff = ((size_t)b * 3 * CC + (size_t)hd * 192) * TT;
    const bf16* qph = qkvh + hoff;
    const bf16* qpl = qkvl + hoff;
    const bf16* kph = qph + (size_t)64 * TT;
    const bf16* kpl = qpl + (size_t)64 * TT;
    const bf16* vph = kph + (size_t)64 * TT;
    const bf16* vpl = kpl + (size_t)64 * TT;

    int crow[2], cc16[2];
    #pragma unroll
    for (int it = 0; it < 2; it++) {
        int e = tid + it * 256;
        crow[it] = e >> 3;
        cc16[it] = e & 7;
    }

    #pragma unroll
    for (int it = 0; it < 2; it++) {
        uint32_t doff = (uint32_t)(crow[it] * 72 + cc16[it] * 8) * 2;
        size_t soff = (size_t)crow[it] * TT + q0g + cc16[it] * 8;
        cpa16(uQ + doff, qph + soff);
        cpa16(uQ + SIDEB + doff, qpl + soff);
    }
    cpa_commit();
    if (tid < 64) { m_s[tid] = -1e30f; l_s[tid] = 0.f; }

    float o[4][4];
    #pragma unroll
    for (int i = 0; i < 4; i++)
        #pragma unroll
        for (int j = 0; j < 4; j++) o[i][j] = 0.f;

    uint32_t qk_a_off = (((lane & 7) + ((lane & 16) ? 8 : 0)) * 72 +
                         qbase + ((lane & 8) ? 8 : 0)) * 2;
    uint32_t qk_b_off[2];
    #pragma unroll
    for (int h = 0; h < 2; h++)
        qk_b_off[h] = ((lane & 15) * 72 + sbase + h * 16 + ((lane & 16) ? 8 : 0)) * 2;
    uint32_t pv_a_off = ((qbase + (lane & 15)) * 72 + ((lane & 16) ? 8 : 0)) * 2;
    uint32_t pv_b_off[2];
    #pragma unroll
    for (int h = 0; h < 2; h++)
        pv_b_off[h] = ((ws * 32 + h * 16 + (lane & 7) + ((lane & 16) ? 8 : 0)) * 72 +
                       ((lane & 8) ? 8 : 0)) * 2;

    cpa_wait0();
    __syncthreads();

    uint32_t qh[4][4], ql[4][4];
    #pragma unroll
    for (int cs = 0; cs < 4; cs++) {
        uint32_t coff = cs * 16 * 72 * 2;
        ldsm4t(qh[cs], uQ + qk_a_off + coff);
        ldsm4t(ql[cs], uQ + SIDEB + qk_a_off + coff);
    }

    for (int kt = 0; kt < TT / 64; kt++) {
        int s0g = kt * 64;
        #pragma unroll
        for (int it = 0; it < 2; it++) {
            uint32_t doff = (uint32_t)(crow[it] * 72 + cc16[it] * 8) * 2;
            size_t soff = (size_t)crow[it] * TT + s0g + cc16[it] * 8;
            cpa16(uK + doff, kph + soff);
            cpa16(uK + SIDEB + doff, kpl + soff);
            cpa16(uV + doff, vph + soff);
            cpa16(uV + SIDEB + doff, vpl + soff);
        }
        cpa_commit();
        cpa_wait0();
        __syncthreads();

        // ---- QK ----
        {
            float sc[4][4];
            #pragma unroll
            for (int i = 0; i < 4; i++)
                #pragma unroll
                for (int j = 0; j < 4; j++) sc[i][j] = 0.f;
            #pragma unroll
            for (int cs = 0; cs < 4; cs++) {
                uint32_t coff = cs * 16 * 72 * 2;
                uint32_t bh[2][4], bl[2][4];
                #pragma unroll
                for (int h = 0; h < 2; h++) {
                    ldsm4t(bh[h], uK + qk_b_off[h] + coff);
                    ldsm4t(bl[h], uK + SIDEB + qk_b_off[h] + coff);
                }
                #pragma unroll
                for (int nt = 0; nt < 4; nt++) {
                    uint32_t* B_h = &bh[nt >> 1][(nt & 1) * 2];
                    uint32_t* B_l = &bl[nt >> 1][(nt & 1) * 2];
                    mma16816(sc[nt], qh[cs], B_h);
                    mma16816(sc[nt], ql[cs], B_h);
                    mma16816(sc[nt], qh[cs], B_l);
                }
            }
            int r0 = qbase + (lane >> 2);
            #pragma unroll
            for (int nt = 0; nt < 4; nt++) {
                int cc = sbase + nt * 8 + (lane & 3) * 2;
                *(float2*)&sS[r0 * 68 + cc] =
                    make_float2(sc[nt][0] * 0.125f, sc[nt][1] * 0.125f);
                *(float2*)&sS[(r0 + 8) * 68 + cc] =
                    make_float2(sc[nt][2] * 0.125f, sc[nt][3] * 0.125f);
            }
        }
        __syncthreads();

        // ---- softmax ----
        {
            int q = tid >> 2, part = tid & 3;
            float pv[16];
            #pragma unroll
            for (int j4 = 0; j4 < 4; j4++)
                *(float4*)&pv[j4 * 4] = *(const float4*)&sS[q * 68 + part * 16 + j4 * 4];
            float mprev = m_s[q];
            float mx = -1e30f;
            #pragma unroll
            for (int j = 0; j < 16; j++) mx = fmaxf(mx, pv[j]);
            mx = fmaxf(mx, __shfl_xor_sync(0xffffffffu, mx, 1));
            mx = fmaxf(mx, __shfl_xor_sync(0xffffffffu, mx, 2));
            mx = fmaxf(mx, mprev);
            float sum = 0.f;
            #pragma unroll
            for (int j = 0; j < 16; j++) { pv[j] = __expf(pv[j] - mx); sum += pv[j]; }
            sum += __shfl_xor_sync(0xffffffffu, sum, 1);
            sum += __shfl_xor_sync(0xffffffffu, sum, 2);
            #pragma unroll
            for (int j4 = 0; j4 < 4; j4++) {
                uint32_t h0, l0, h1, l1;
                split2(pv[j4 * 4], pv[j4 * 4 + 1], h0, l0);
                split2(pv[j4 * 4 + 2], pv[j4 * 4 + 3], h1, l1);
                *(uint2*)&sP[q * 72 + part * 16 + j4 * 4] = make_uint2(h0, h1);
                *(uint2*)&sP[SIDE + q * 72 + part * 16 + j4 * 4] = make_uint2(l0, l1);
            }
            if (part == 0) {
                float al = __expf(mprev - mx);
                m_s[q] = mx;
                al_s[q] = al;
                l_s[q] = l_s[q] * al + sum;
            }
        }
        __syncthreads();

        // ---- PV ----
        {
            float al0 = al_s[qbase + (lane >> 2)];
            float al1 = al_s[qbase + (lane >> 2) + 8];
            #pragma unroll
            for (int nt = 0; nt < 4; nt++) {
                o[nt][0] *= al0; o[nt][1] *= al0;
                o[nt][2] *= al1; o[nt][3] *= al1;
            }
            #pragma unroll
            for (int st = 0; st < 4; st++) {
                uint32_t soff = st * 16 * 2;
                uint32_t pah[4], pal[4], vbh[2][4], vbl[2][4];
                ldsm4(pah, uP + pv_a_off + soff);
                ldsm4(pal, uP + SIDEB + pv_a_off + soff);
                #pragma unroll
                for (int h = 0; h < 2; h++) {
                    ldsm4(vbh[h], uV + pv_b_off[h] + soff);
                    ldsm4(vbl[h], uV + SIDEB + pv_b_off[h] + soff);
                }
                #pragma unroll
                for (int nt = 0; nt < 4; nt++) {
                    uint32_t* B_h = &vbh[nt >> 1][(nt & 1) * 2];
                    uint32_t* B_l = &vbl[nt >> 1][(nt & 1) * 2];
                    mma16816(o[nt], pah, B_h);
                    mma16816(o[nt], pal, B_h);
                    mma16816(o[nt], pah, B_l);
                }
            }
        }
        __syncthreads();
    }

    // normalize + stage [c][q], split-store planes
    {
        float li0 = 1.f / l_s[qbase + (lane >> 2)];
        float li1 = 1.f / l_s[qbase + (lane >> 2) + 8];
        int qq = qbase + (lane >> 2);
        #pragma unroll
        for (int nt = 0; nt < 4; nt++) {
            int c0 = ws * 32 + nt * 8 + (lane & 3) * 2;
            sS[c0 * 68 + qq] = o[nt][0] * li0;
            sS[(c0 + 1) * 68 + qq] = o[nt][1] * li0;
            sS[c0 * 68 + qq + 8] = o[nt][2] * li1;
            sS[(c0 + 1) * 68 + qq + 8] = o[nt][3] * li1;
        }
    }
    __syncthreads();
    size_t obase = ((size_t)b * CC + (size_t)hd * 64) * TT + q0g;
    #pragma unroll
    for (int it = 0; it < 4; it++) {
        int e = tid + it * 256;
        int cch = e >> 4, q4 = e & 15;
        float4 v = *(const float4*)&sS[cch * 68 + q4 * 4];
        uint32_t h0, l0, h1, l1;
        split2(v.x, v.y, h0, l0); split2(v.z, v.w, h1, l1);
        *(uint2*)&ath[obase + (size_t)cch * TT + q4 * 4] = make_uint2(h0, h1);
        *(uint2*)&atl[obase + (size_t)cch * TT + q4 * 4] = make_uint2(l0, l1);
    }
}

// ---------------------------------------------------------------------------
extern "C" void kernel_launch(void* const* d_in, const int* in_sizes, int n_in,
                              void* d_out, int out_size) {
    const float* x = (const float*)d_in[0];
    const float* gn_scale = (const float*)d_in[1];
    const float* gn_bias = (const float*)d_in[2];
    const float* w_qkv = (const float*)d_in[3];
    const float* b_qkv = (const float*)d_in[4];
    const float* w_proj = (const float*)d_in[5];
    const float* b_proj = (const float*)d_in[6];
    float* out = (float*)d_out;

    bf16 *xnh, *xnl, *qkvh, *qkvl, *ath, *atl, *wqh, *wql, *wph, *wpl;
    cudaGetSymbolAddress((void**)&xnh, g_xn_h);
    cudaGetSymbolAddress((void**)&xnl, g_xn_l);
    cudaGetSymbolAddress((void**)&qkvh, g_qkv_h);
    cudaGetSymbolAddress((void**)&qkvl, g_qkv_l);
    cudaGetSymbolAddress((void**)&ath, g_at_h);
    cudaGetSymbolAddress((void**)&atl, g_at_l);
    cudaGetSymbolAddress((void**)&wqh, g_wq_h);
    cudaGetSymbolAddress((void**)&wql, g_wq_l);
    cudaGetSymbolAddress((void**)&wph, g_wp_h);
    cudaGetSymbolAddress((void**)&wpl, g_wp_l);

    cudaFuncSetAttribute(attn_mma, cudaFuncAttributeMaxDynamicSharedMemorySize,
                         ATTN_SMEM);

    wsplit_kernel<<<(3 * CC * CC / 2 + 255) / 256, 256>>>(w_qkv, wqh, wql, 3 * CC * CC);
    wsplit_kernel<<<(CC * CC / 2 + 255) / 256, 256>>>(w_proj, wph, wpl, CC * CC);
    gn_kernel<<<BB * NG, 256>>>(x, gn_scale, gn_bias, xnh, xnl);
    gemm_mma<true><<<dim3(TT / 128, (3 * CC) / 128, BB), 256>>>(
        wqh, wql, xnh, xnl, b_qkv, nullptr, nullptr, qkvh, qkvl, 3 * CC, CC);
    attn_mma<<<dim3(TT / 64, BB * NH), 256, ATTN_SMEM>>>(qkvh, qkvl, ath, atl);
    gemm_mma<false><<<dim3(TT / 128, CC / 128, BB), 256>>>(
        wph, wpl, ath, atl, b_proj, x, out, nullptr, nullptr, CC, CC);
}

// round 15
// speedup vs baseline: 1.9229x; 1.0445x over previous
#include <cuda_runtime.h>
#include <cuda_bf16.h>
#include <cstdint>

#define BB 16
#define CC 512
#define TT 1024
#define NH 8
#define DH 64
#define NG 32
#define CPG 16

typedef __nv_bfloat16 bf16;

// ---------------- scratch ----------------
__device__ bf16 g_xn_h[BB * CC * TT];
__device__ bf16 g_xn_l[BB * CC * TT];
__device__ bf16 g_qkv_h[BB * 3 * CC * TT];
__device__ bf16 g_qkv_l[BB * 3 * CC * TT];
__device__ bf16 g_at_h[BB * CC * TT];
__device__ bf16 g_at_l[BB * CC * TT];
__device__ bf16 g_wq_h[3 * CC * CC];
__device__ bf16 g_wq_l[3 * CC * CC];
__device__ bf16 g_wp_h[CC * CC];
__device__ bf16 g_wp_l[CC * CC];

// ---------------- helpers ----------------
__device__ __forceinline__ uint32_t cvta_smem(const void* p) {
    uint32_t a;
    asm("{.reg .u64 t; cvta.to.shared.u64 t, %1; cvt.u32.u64 %0, t;}"
        : "=r"(a) : "l"(p));
    return a;
}
__device__ __forceinline__ void ldsm4(uint32_t* r, uint32_t addr) {
    asm volatile("ldmatrix.sync.aligned.m8n8.x4.shared.b16 {%0,%1,%2,%3},[%4];"
                 : "=r"(r[0]), "=r"(r[1]), "=r"(r[2]), "=r"(r[3]) : "r"(addr));
}
__device__ __forceinline__ void ldsm4t(uint32_t* r, uint32_t addr) {
    asm volatile("ldmatrix.sync.aligned.m8n8.x4.trans.shared.b16 {%0,%1,%2,%3},[%4];"
                 : "=r"(r[0]), "=r"(r[1]), "=r"(r[2]), "=r"(r[3]) : "r"(addr));
}
__device__ __forceinline__ void mma16816(float* c, const uint32_t* a, const uint32_t* b) {
    asm volatile(
        "mma.sync.aligned.m16n8k16.row.col.f32.bf16.bf16.f32 "
        "{%0,%1,%2,%3},{%4,%5,%6,%7},{%8,%9},{%0,%1,%2,%3};"
        : "+f"(c[0]), "+f"(c[1]), "+f"(c[2]), "+f"(c[3])
        : "r"(a[0]), "r"(a[1]), "r"(a[2]), "r"(a[3]), "r"(b[0]), "r"(b[1]));
}
__device__ __forceinline__ void cpa16(uint32_t dst, const void* src) {
    asm volatile("cp.async.cg.shared.global [%0],[%1],16;" :: "r"(dst), "l"(src));
}
__device__ __forceinline__ void cpa_commit() {
    asm volatile("cp.async.commit_group;");
}
__device__ __forceinline__ void cpa_wait0() {
    asm volatile("cp.async.wait_group 0;");
}
__device__ __forceinline__ void cpa_wait1() {
    asm volatile("cp.async.wait_group 1;");
}
union BF2U { __nv_bfloat162 h; uint32_t u; };
__device__ __forceinline__ void split2(float x, float y, uint32_t& hi, uint32_t& lo) {
    BF2U H, L;
    H.h = __floats2bfloat162_rn(x, y);
    float rx = x - __low2float(H.h);
    float ry = y - __high2float(H.h);
    L.h = __floats2bfloat162_rn(rx, ry);
    hi = H.u; lo = L.u;
}

// ---------------------------------------------------------------------------
// W pre-split: f32 -> bf16 hi/lo planes
// ---------------------------------------------------------------------------
__global__ void wsplit_kernel(const float* __restrict__ w, bf16* __restrict__ wh,
                              bf16* __restrict__ wl, int n) {
    int i = (blockIdx.x * blockDim.x + threadIdx.x) * 2;
    if (i < n) {
        uint32_t h, l;
        split2(w[i], w[i + 1], h, l);
        *(uint32_t*)&wh[i] = h;
        *(uint32_t*)&wl[i] = l;
    }
}

// ---------------------------------------------------------------------------
// GroupNorm -> bf16 hi/lo planes
// ---------------------------------------------------------------------------
__global__ __launch_bounds__(256) void gn_kernel(
    const float* __restrict__ x, const float* __restrict__ scale,
    const float* __restrict__ bias, bf16* __restrict__ xnh,
    bf16* __restrict__ xnl) {
    int blk = blockIdx.x;
    int b = blk >> 5, g = blk & 31;
    size_t base = ((size_t)b * CC + (size_t)g * CPG) * TT;
    const float4* xp4 = (const float4*)(x + base);
    const int N4 = CPG * TT / 4;

    float s = 0.f, ss = 0.f;
    for (int i = threadIdx.x; i < N4; i += 256) {
        float4 v = xp4[i];
        s += v.x + v.y + v.z + v.w;
        ss += v.x * v.x + v.y * v.y + v.z * v.z + v.w * v.w;
    }
    for (int o = 16; o; o >>= 1) {
        s += __shfl_down_sync(0xffffffffu, s, o);
        ss += __shfl_down_sync(0xffffffffu, ss, o);
    }
    __shared__ float red0[8], red1[8];
    __shared__ float mean_s, inv_s;
    int warp = threadIdx.x >> 5, lane = threadIdx.x & 31;
    if (lane == 0) { red0[warp] = s; red1[warp] = ss; }
    __syncthreads();
    if (threadIdx.x == 0) {
        float S = 0.f, SS = 0.f;
        #pragma unroll
        for (int w = 0; w < 8; w++) { S += red0[w]; SS += red1[w]; }
        const float invn = 1.f / (float)(CPG * TT);
        float mean = S * invn;
        float var = SS * invn - mean * mean;
        mean_s = mean;
        inv_s = rsqrtf(var + 1e-5f);
    }
    __syncthreads();
    float mean = mean_s, inv = inv_s;
    for (int i = threadIdx.x; i < N4; i += 256) {
        int ch = g * CPG + (i >> 8);
        float sc = scale[ch] * inv, bi = bias[ch] - mean * sc;
        float4 v = xp4[i];
        v.x = v.x * sc + bi; v.y = v.y * sc + bi;
        v.z = v.z * sc + bi; v.w = v.w * sc + bi;
        uint32_t h0, l0, h1, l1;
        split2(v.x, v.y, h0, l0); split2(v.z, v.w, h1, l1);
        *(uint2*)&xnh[base + (size_t)i * 4] = make_uint2(h0, h1);
        *(uint2*)&xnl[base + (size_t)i * 4] = make_uint2(l0, l1);
    }
}

// ---------------------------------------------------------------------------
// GEMM (R12/R14-proven, unchanged): 128x128 block, 8 warps, 2-stage cp.async.
// ---------------------------------------------------------------------------
#define A_ST 12288u
#define A_SD 6144u
#define B_ST 8704u
#define B_SD 4352u

template <bool PO>
__global__ __launch_bounds__(256, 2) void gemm_mma(
    const bf16* __restrict__ Wh, const bf16* __restrict__ Wl,
    const bf16* __restrict__ Xh, const bf16* __restrict__ Xl,
    const float* __restrict__ bias, const float* __restrict__ res,
    float* __restrict__ outf, bf16* __restrict__ oh, bf16* __restrict__ ol,
    int M, int K) {
    const int N = TT;
    int bb = blockIdx.z;
    size_t xoff = (size_t)bb * K * N;

    __shared__ __align__(16) bf16 sA[2][2][128][24];
    __shared__ __align__(16) bf16 sB[2][2][16][136];
    const uint32_t uA = cvta_smem(sA);
    const uint32_t uB = cvta_smem(sB);

    int tid = threadIdx.x, lane = tid & 31, warp = tid >> 5;
    int wm = warp >> 2, wn = warp & 3;
    int m0 = blockIdx.y * 128, n0 = blockIdx.x * 128;
    const int NT = K / 16;

    auto issue = [&](int kt, int buf) {
        #pragma unroll
        for (int it = 0; it < 2; it++) {
            int e = tid + it * 256;
            int side = e >> 8, m = (e >> 1) & 127, ch = e & 1;
            const bf16* src = (side ? Wl : Wh) + (size_t)(m0 + m) * K + kt * 16 + ch * 8;
            cpa16(uA + buf * A_ST + side * A_SD + (uint32_t)(m * 24 + ch * 8) * 2, src);
        }
        #pragma unroll
        for (int it = 0; it < 2; it++) {
            int e = tid + it * 256;
            int side = e >> 8, row = (e >> 4) & 15, c16 = e & 15;
            const bf16* src = (side ? Xl : Xh) + xoff + (size_t)(kt * 16 + row) * N + n0 + c16 * 8;
            cpa16(uB + buf * B_ST + side * B_SD + (uint32_t)(row * 136 + c16 * 8) * 2, src);
        }
        cpa_commit();
    };

    uint32_t aoff[4], boff[2];
    {
        int arow = lane & 15, acol = (lane & 16) ? 8 : 0;
        #pragma unroll
        for (int mt = 0; mt < 4; mt++)
            aoff[mt] = ((wm * 64 + mt * 16 + arow) * 24 + acol) * 2;
        int bkr = lane & 15, bnc = (lane & 16) ? 8 : 0;
        #pragma unroll
        for (int h = 0; h < 2; h++)
            boff[h] = (bkr * 136 + wn * 32 + h * 16 + bnc) * 2;
    }

    float c[4][4][4];
    #pragma unroll
    for (int i = 0; i < 4; i++)
        #pragma unroll
        for (int j = 0; j < 4; j++)
            #pragma unroll
            for (int k = 0; k < 4; k++) c[i][j][k] = 0.f;

    issue(0, 0);
    cpa_wait0();
    __syncthreads();

    for (int kt = 0; kt < NT; kt++) {
        int cur = kt & 1;
        if (kt + 1 < NT) issue(kt + 1, cur ^ 1);

        uint32_t aB = uA + cur * A_ST;
        uint32_t bB = uB + cur * B_ST;
        uint32_t bh[2][4], bl[2][4];
        #pragma unroll
        for (int h = 0; h < 2; h++) {
            ldsm4t(bh[h], bB + boff[h]);
            ldsm4t(bl[h], bB + B_SD + boff[h]);
        }
        #pragma unroll
        for (int mt = 0; mt < 4; mt++) {
            uint32_t ah[4], al[4];
            ldsm4(ah, aB + aoff[mt]);
            ldsm4(al, aB + A_SD + aoff[mt]);
            #pragma unroll
            for (int nt = 0; nt < 4; nt++) {
                uint32_t* B_h = &bh[nt >> 1][(nt & 1) * 2];
                uint32_t* B_l = &bl[nt >> 1][(nt & 1) * 2];
                mma16816(c[mt][nt], ah, B_h);
                mma16816(c[mt][nt], al, B_h);
                mma16816(c[mt][nt], ah, B_l);
            }
        }
        if (kt + 1 < NT) {
            cpa_wait0();
            __syncthreads();
        }
    }

    #pragma unroll
    for (int mt = 0; mt < 4; mt++) {
        int r0 = m0 + wm * 64 + mt * 16 + (lane >> 2);
        int r1 = r0 + 8;
        float b0v = bias[r0], b1v = bias[r1];
        #pragma unroll
        for (int nt = 0; nt < 4; nt++) {
            int cc = n0 + wn * 32 + nt * 8 + (lane & 3) * 2;
            float v00 = c[mt][nt][0] + b0v, v01 = c[mt][nt][1] + b0v;
            float v10 = c[mt][nt][2] + b1v, v11 = c[mt][nt][3] + b1v;
            size_t i0 = (size_t)bb * M * N + (size_t)r0 * N + cc;
            size_t i1 = (size_t)bb * M * N + (size_t)r1 * N + cc;
            if (PO) {
                uint32_t h, l;
                split2(v00, v01, h, l);
                *(uint32_t*)&oh[i0] = h; *(uint32_t*)&ol[i0] = l;
                split2(v10, v11, h, l);
                *(uint32_t*)&oh[i1] = h; *(uint32_t*)&ol[i1] = l;
            } else {
                float2 v0 = {v00, v01}, v1 = {v10, v11};
                if (res) {
                    float2 q0 = *(const float2*)&res[i0];
                    float2 q1 = *(const float2*)&res[i1];
                    v0.x += q0.x; v0.y += q0.y; v1.x += q1.x; v1.y += q1.y;
                }
                *(float2*)&outf[i0] = v0;
                *(float2*)&outf[i1] = v1;
            }
        }
    }
}

// ---------------------------------------------------------------------------
// Attention — R14-proven compact 2-CTA map; NEW: split K/V prefetch.
// K issued after post-QK sync (lands during softmax+PV); V issued after
// post-PV sync (lands during next QK+softmax). wait1 fences exactly the
// group needed; smem map and all fragment offsets byte-identical to R14.
// ---------------------------------------------------------------------------
#define O_Q 0
#define O_K 18432
#define O_V 36864
#define O_P 55296
#define O_S 73728
#define O_M 91136
#define O_L 91392
#define O_AL 91648
#define ATTN_SMEM 91904
#define SIDEB (64 * 72 * 2)

__global__ __launch_bounds__(256, 2) void attn_mma(
    const bf16* __restrict__ qkvh, const bf16* __restrict__ qkvl,
    bf16* __restrict__ ath, bf16* __restrict__ atl) {
    extern __shared__ char smem[];
    bf16* sP = (bf16*)(smem + O_P);
    float* sS = (float*)(smem + O_S);
    float* m_s = (float*)(smem + O_M);
    float* l_s = (float*)(smem + O_L);
    float* al_s = (float*)(smem + O_AL);
    const int SIDE = 64 * 72;

    const uint32_t uQ = cvta_smem(smem + O_Q);
    const uint32_t uK = cvta_smem(smem + O_K);
    const uint32_t uV = cvta_smem(smem + O_V);
    const uint32_t uP = cvta_smem(sP);

    int tid = threadIdx.x, lane = tid & 31, warp = tid >> 5;
    int wq = warp >> 1, ws = warp & 1;
    int qbase = wq * 16, sbase = ws * 32;
    int head = blockIdx.y;
    int b = head >> 3, hd = head & 7;
    int q0g = blockIdx.x * 64;

    size_t hoff = ((size_t)b * 3 * CC + (size_t)hd * 192) * TT;
    const bf16* qph = qkvh + hoff;
    const bf16* qpl = qkvl + hoff;
    const bf16* kph = qph + (size_t)64 * TT;
    const bf16* kpl = qpl + (size_t)64 * TT;
    const bf16* vph = kph + (size_t)64 * TT;
    const bf16* vpl = kpl + (size_t)64 * TT;

    int crow[2], cc16[2];
    #pragma unroll
    for (int it = 0; it < 2; it++) {
        int e = tid + it * 256;
        crow[it] = e >> 3;
        cc16[it] = e & 7;
    }

    auto issueK = [&](int kt) {
        int s0g = kt * 64;
        #pragma unroll
        for (int it = 0; it < 2; it++) {
            uint32_t doff = (uint32_t)(crow[it] * 72 + cc16[it] * 8) * 2;
            size_t soff = (size_t)crow[it] * TT + s0g + cc16[it] * 8;
            cpa16(uK + doff, kph + soff);
            cpa16(uK + SIDEB + doff, kpl + soff);
        }
        cpa_commit();
    };
    auto issueV = [&](int kt) {
        int s0g = kt * 64;
        #pragma unroll
        for (int it = 0; it < 2; it++) {
            uint32_t doff = (uint32_t)(crow[it] * 72 + cc16[it] * 8) * 2;
            size_t soff = (size_t)crow[it] * TT + s0g + cc16[it] * 8;
            cpa16(uV + doff, vph + soff);
            cpa16(uV + SIDEB + doff, vpl + soff);
        }
        cpa_commit();
    };

    // prologue: group0 = Q + K(0); group1 = V(0)
    #pragma unroll
    for (int it = 0; it < 2; it++) {
        uint32_t doff = (uint32_t)(crow[it] * 72 + cc16[it] * 8) * 2;
        size_t soff = (size_t)crow[it] * TT + q0g + cc16[it] * 8;
        cpa16(uQ + doff, qph + soff);
        cpa16(uQ + SIDEB + doff, qpl + soff);
    }
    {
        #pragma unroll
        for (int it = 0; it < 2; it++) {
            uint32_t doff = (uint32_t)(crow[it] * 72 + cc16[it] * 8) * 2;
            size_t soff = (size_t)crow[it] * TT + cc16[it] * 8;
            cpa16(uK + doff, kph + soff);
            cpa16(uK + SIDEB + doff, kpl + soff);
        }
    }
    cpa_commit();
    issueV(0);

    if (tid < 64) { m_s[tid] = -1e30f; l_s[tid] = 0.f; }

    float o[4][4];
    #pragma unroll
    for (int i = 0; i < 4; i++)
        #pragma unroll
        for (int j = 0; j < 4; j++) o[i][j] = 0.f;

    uint32_t qk_a_off = (((lane & 7) + ((lane & 16) ? 8 : 0)) * 72 +
                         qbase + ((lane & 8) ? 8 : 0)) * 2;
    uint32_t qk_b_off[2];
    #pragma unroll
    for (int h = 0; h < 2; h++)
        qk_b_off[h] = ((lane & 15) * 72 + sbase + h * 16 + ((lane & 16) ? 8 : 0)) * 2;
    uint32_t pv_a_off = ((qbase + (lane & 15)) * 72 + ((lane & 16) ? 8 : 0)) * 2;
    uint32_t pv_b_off[2];
    #pragma unroll
    for (int h = 0; h < 2; h++)
        pv_b_off[h] = ((ws * 32 + h * 16 + (lane & 7) + ((lane & 16) ? 8 : 0)) * 72 +
                       ((lane & 8) ? 8 : 0)) * 2;

    cpa_wait1();     // Q + K(0) ready (V(0) may still be in flight)
    __syncthreads();

    uint32_t qh[4][4], ql[4][4];
    #pragma unroll
    for (int cs = 0; cs < 4; cs++) {
        uint32_t coff = cs * 16 * 72 * 2;
        ldsm4t(qh[cs], uQ + qk_a_off + coff);
        ldsm4t(ql[cs], uQ + SIDEB + qk_a_off + coff);
    }

    const int NKT = TT / 64;
    for (int kt = 0; kt < NKT; kt++) {
        // ---- QK (K(kt) ready: prologue wait for kt=0, loop-bottom wait else) ----
        {
            float sc[4][4];
            #pragma unroll
            for (int i = 0; i < 4; i++)
                #pragma unroll
                for (int j = 0; j < 4; j++) sc[i][j] = 0.f;
            #pragma unroll
            for (int cs = 0; cs < 4; cs++) {
                uint32_t coff = cs * 16 * 72 * 2;
                uint32_t bh[2][4], bl[2][4];
                #pragma unroll
                for (int h = 0; h < 2; h++) {
                    ldsm4t(bh[h], uK + qk_b_off[h] + coff);
                    ldsm4t(bl[h], uK + SIDEB + qk_b_off[h] + coff);
                }
                #pragma unroll
                for (int nt = 0; nt < 4; nt++) {
                    uint32_t* B_h = &bh[nt >> 1][(nt & 1) * 2];
                    uint32_t* B_l = &bl[nt >> 1][(nt & 1) * 2];
                    mma16816(sc[nt], qh[cs], B_h);
                    mma16816(sc[nt], ql[cs], B_h);
                    mma16816(sc[nt], qh[cs], B_l);
                }
            }
            int r0 = qbase + (lane >> 2);
            #pragma unroll
            for (int nt = 0; nt < 4; nt++) {
                int cc = sbase + nt * 8 + (lane & 3) * 2;
                *(float2*)&sS[r0 * 68 + cc] =
                    make_float2(sc[nt][0] * 0.125f, sc[nt][1] * 0.125f);
                *(float2*)&sS[(r0 + 8) * 68 + cc] =
                    make_float2(sc[nt][2] * 0.125f, sc[nt][3] * 0.125f);
            }
        }
        __syncthreads();               // S written; K buffer free

        if (kt + 1 < NKT) issueK(kt + 1);   // lands during softmax + PV

        // ---- softmax ----
        {
            int q = tid >> 2, part = tid & 3;
            float pv[16];
            #pragma unroll
            for (int j4 = 0; j4 < 4; j4++)
                *(float4*)&pv[j4 * 4] = *(const float4*)&sS[q * 68 + part * 16 + j4 * 4];
            float mprev = m_s[q];
            float mx = -1e30f;
            #pragma unroll
            for (int j = 0; j < 16; j++) mx = fmaxf(mx, pv[j]);
            mx = fmaxf(mx, __shfl_xor_sync(0xffffffffu, mx, 1));
            mx = fmaxf(mx, __shfl_xor_sync(0xffffffffu, mx, 2));
            mx = fmaxf(mx, mprev);
            float sum = 0.f;
            #pragma unroll
            for (int j = 0; j < 16; j++) { pv[j] = __expf(pv[j] - mx); sum += pv[j]; }
            sum += __shfl_xor_sync(0xffffffffu, sum, 1);
            sum += __shfl_xor_sync(0xffffffffu, sum, 2);
            #pragma unroll
            for (int j4 = 0; j4 < 4; j4++) {
                uint32_t h0, l0, h1, l1;
                split2(pv[j4 * 4], pv[j4 * 4 + 1], h0, l0);
                split2(pv[j4 * 4 + 2], pv[j4 * 4 + 3], h1, l1);
                *(uint2*)&sP[q * 72 + part * 16 + j4 * 4] = make_uint2(h0, h1);
                *(uint2*)&sP[SIDE + q * 72 + part * 16 + j4 * 4] = make_uint2(l0, l1);
            }
            if (part == 0) {
                float al = __expf(mprev - mx);
                m_s[q] = mx;
                al_s[q] = al;
                l_s[q] = l_s[q] * al + sum;
            }
        }
        // fence V(kt): pending groups are {V(kt)[, K(kt+1)]} — oldest first
        if (kt + 1 < NKT) cpa_wait1(); else cpa_wait0();
        __syncthreads();               // P + stats visible; V(kt) visible

        // ---- PV ----
        {
            float al0 = al_s[qbase + (lane >> 2)];
            float al1 = al_s[qbase + (lane >> 2) + 8];
            #pragma unroll
            for (int nt = 0; nt < 4; nt++) {
                o[nt][0] *= al0; o[nt][1] *= al0;
                o[nt][2] *= al1; o[nt][3] *= al1;
            }
            #pragma unroll
            for (int st = 0; st < 4; st++) {
                uint32_t soff = st * 16 * 2;
                uint32_t pah[4], pal[4], vbh[2][4], vbl[2][4];
                ldsm4(pah, uP + pv_a_off + soff);
                ldsm4(pal, uP + SIDEB + pv_a_off + soff);
                #pragma unroll
                for (int h = 0; h < 2; h++) {
                    ldsm4(vbh[h], uV + pv_b_off[h] + soff);
                    ldsm4(vbl[h], uV + SIDEB + pv_b_off[h] + soff);
                }
                #pragma unroll
                for (int nt = 0; nt < 4; nt++) {
                    uint32_t* B_h = &vbh[nt >> 1][(nt & 1) * 2];
                    uint32_t* B_l = &vbl[nt >> 1][(nt & 1) * 2];
                    mma16816(o[nt], pah, B_h);
                    mma16816(o[nt], pal, B_h);
                    mma16816(o[nt], pah, B_l);
                }
            }
        }
        __syncthreads();               // V buffer free

        if (kt + 1 < NKT) issueV(kt + 1);   // lands during next QK + softmax

        if (kt + 1 < NKT) {
            // fence K(kt+1): pending groups are {K(kt+1), V(kt+1)} — oldest first
            cpa_wait1();
            __syncthreads();
        }
    }

    // normalize + stage [c][q], split-store planes
    {
        float li0 = 1.f / l_s[qbase + (lane >> 2)];
        float li1 = 1.f / l_s[qbase + (lane >> 2) + 8];
        int qq = qbase + (lane >> 2);
        #pragma unroll
        for (int nt = 0; nt < 4; nt++) {
            int c0 = ws * 32 + nt * 8 + (lane & 3) * 2;
            sS[c0 * 68 + qq] = o[nt][0] * li0;
            sS[(c0 + 1) * 68 + qq] = o[nt][1] * li0;
            sS[c0 * 68 + qq + 8] = o[nt][2] * li1;
            sS[(c0 + 1) * 68 + qq + 8] = o[nt][3] * li1;
        }
    }
    __syncthreads();
    size_t obase = ((size_t)b * CC + (size_t)hd * 64) * TT + q0g;
    #pragma unroll
    for (int it = 0; it < 4; it++) {
        int e = tid + it * 256;
        int cch = e >> 4, q4 = e & 15;
        float4 v = *(const float4*)&sS[cch * 68 + q4 * 4];
        uint32_t h0, l0, h1, l1;
        split2(v.x, v.y, h0, l0); split2(v.z, v.w, h1, l1);
        *(uint2*)&ath[obase + (size_t)cch * TT + q4 * 4] = make_uint2(h0, h1);
        *(uint2*)&atl[obase + (size_t)cch * TT + q4 * 4] = make_uint2(l0, l1);
    }
}

// ---------------------------------------------------------------------------
extern "C" void kernel_launch(void* const* d_in, const int* in_sizes, int n_in,
                              void* d_out, int out_size) {
    const float* x = (const float*)d_in[0];
    const float* gn_scale = (const float*)d_in[1];
    const float* gn_bias = (const float*)d_in[2];
    const float* w_qkv = (const float*)d_in[3];
    const float* b_qkv = (const float*)d_in[4];
    const float* w_proj = (const float*)d_in[5];
    const float* b_proj = (const float*)d_in[6];
    float* out = (float*)d_out;

    bf16 *xnh, *xnl, *qkvh, *qkvl, *ath, *atl, *wqh, *wql, *wph, *wpl;
    cudaGetSymbolAddress((void**)&xnh, g_xn_h);
    cudaGetSymbolAddress((void**)&xnl, g_xn_l);
    cudaGetSymbolAddress((void**)&qkvh, g_qkv_h);
    cudaGetSymbolAddress((void**)&qkvl, g_qkv_l);
    cudaGetSymbolAddress((void**)&ath, g_at_h);
    cudaGetSymbolAddress((void**)&atl, g_at_l);
    cudaGetSymbolAddress((void**)&wqh, g_wq_h);
    cudaGetSymbolAddress((void**)&wql, g_wq_l);
    cudaGetSymbolAddress((void**)&wph, g_wp_h);
    cudaGetSymbolAddress((void**)&wpl, g_wp_l);

    cudaFuncSetAttribute(attn_mma, cudaFuncAttributeMaxDynamicSharedMemorySize,
                         ATTN_SMEM);

    wsplit_kernel<<<(3 * CC * CC / 2 + 255) / 256, 256>>>(w_qkv, wqh, wql, 3 * CC * CC);
    wsplit_kernel<<<(CC * CC / 2 + 255) / 256, 256>>>(w_proj, wph, wpl, CC * CC);
    gn_kernel<<<BB * NG, 256>>>(x, gn_scale, gn_bias, xnh, xnl);
    gemm_mma<true><<<dim3(TT / 128, (3 * CC) / 128, BB), 256>>>(
        wqh, wql, xnh, xnl, b_qkv, nullptr, nullptr, qkvh, qkvl, 3 * CC, CC);
    attn_mma<<<dim3(TT / 64, BB * NH), 256, ATTN_SMEM>>>(qkvh, qkvl, ath, atl);
    gemm_mma<false><<<dim3(TT / 128, CC / 128, BB), 256>>>(
        wph, wpl, ath, atl, b_proj, x, out, nullptr, nullptr, CC, CC);
}